// round 1
// baseline (speedup 1.0000x reference)
#include <cuda_runtime.h>
#include <math.h>

#define N_NODES 100000
#define E_MAX   3300000
#define IN_DIM  512
#define HID_DIM 512
#define OUT_DIM 64
#define HOPS    10

// ---------------- scratch (static device globals; no allocations) ----------------
__device__ float g_h1[(size_t)N_NODES * HID_DIM];                 // 204.8 MB
__device__ float g_H[(size_t)(HOPS + 1) * N_NODES * OUT_DIM];     // 281.6 MB
__device__ int   g_deg[N_NODES];
__device__ int   g_rowptr[N_NODES + 1];
__device__ int   g_cursor[N_NODES];
__device__ int   g_scol[E_MAX];
__device__ float g_sw[E_MAX];

// ---------------- GEMM1: h1 = relu(x @ W1 + b1), [M,512]x[512,512] ----------------
__global__ __launch_bounds__(256) void gemm1_relu_kernel(
    const float* __restrict__ A, const float* __restrict__ B,
    const float* __restrict__ bias, int M)
{
    const int K = IN_DIM, N = HID_DIM;
    __shared__ float As[8][128];
    __shared__ float Bs[8][128];

    int tid  = threadIdx.x;
    int brow = blockIdx.x * 128;
    int bcol = blockIdx.y * 128;

    int a_row = tid >> 1;
    int a_col = (tid & 1) * 4;
    int b_row = tid >> 5;
    int b_col = (tid & 31) * 4;
    int ty = tid >> 4;
    int tx = tid & 15;

    float acc[8][8];
#pragma unroll
    for (int i = 0; i < 8; i++)
#pragma unroll
        for (int j = 0; j < 8; j++) acc[i][j] = 0.f;

    bool a_ok = (brow + a_row) < M;
    const float* Aptr = A + (size_t)(brow + a_row) * K + a_col;

    for (int kt = 0; kt < K; kt += 8) {
        float4 av = a_ok ? *(const float4*)(Aptr + kt) : make_float4(0.f, 0.f, 0.f, 0.f);
        float4 bv = *(const float4*)(B + (size_t)(kt + b_row) * N + bcol + b_col);

        As[a_col + 0][a_row] = av.x;
        As[a_col + 1][a_row] = av.y;
        As[a_col + 2][a_row] = av.z;
        As[a_col + 3][a_row] = av.w;
        *(float4*)&Bs[b_row][b_col] = bv;
        __syncthreads();

#pragma unroll
        for (int k = 0; k < 8; k++) {
            float a[8], b[8];
            *(float4*)(a)     = *(const float4*)&As[k][ty * 8];
            *(float4*)(a + 4) = *(const float4*)&As[k][ty * 8 + 4];
            *(float4*)(b)     = *(const float4*)&Bs[k][tx * 8];
            *(float4*)(b + 4) = *(const float4*)&Bs[k][tx * 8 + 4];
#pragma unroll
            for (int i = 0; i < 8; i++)
#pragma unroll
                for (int j = 0; j < 8; j++) acc[i][j] += a[i] * b[j];
        }
        __syncthreads();
    }

#pragma unroll
    for (int i = 0; i < 8; i++) {
        int r = brow + ty * 8 + i;
        if (r >= M) break;
#pragma unroll
        for (int j = 0; j < 8; j += 4) {
            int c = bcol + tx * 8 + j;
            float4 v;
            v.x = fmaxf(acc[i][j + 0] + bias[c + 0], 0.f);
            v.y = fmaxf(acc[i][j + 1] + bias[c + 1], 0.f);
            v.z = fmaxf(acc[i][j + 2] + bias[c + 2], 0.f);
            v.w = fmaxf(acc[i][j + 3] + bias[c + 3], 0.f);
            *(float4*)(g_h1 + (size_t)r * N + c) = v;
        }
    }
}

// ---------------- GEMM2: H0 = h1 @ W2 + b2, [M,512]x[512,64] ----------------
__global__ __launch_bounds__(256) void gemm2_kernel(
    const float* __restrict__ B, const float* __restrict__ bias, int M)
{
    const int K = HID_DIM, N = OUT_DIM;
    __shared__ float As[8][128];
    __shared__ float Bs[8][64];

    int tid  = threadIdx.x;
    int brow = blockIdx.x * 128;

    int a_row = tid >> 1;
    int a_col = (tid & 1) * 4;
    int ty = tid >> 4;  // 0..15 -> 8 rows each
    int tx = tid & 15;  // 0..15 -> 4 cols each

    float acc[8][4];
#pragma unroll
    for (int i = 0; i < 8; i++)
#pragma unroll
        for (int j = 0; j < 4; j++) acc[i][j] = 0.f;

    bool a_ok = (brow + a_row) < M;
    const float* Aptr = g_h1 + (size_t)(brow + a_row) * K + a_col;

    for (int kt = 0; kt < K; kt += 8) {
        float4 av = a_ok ? *(const float4*)(Aptr + kt) : make_float4(0.f, 0.f, 0.f, 0.f);
        float4 bv = make_float4(0.f, 0.f, 0.f, 0.f);
        if (tid < 128)
            bv = *(const float4*)(B + (size_t)(kt + (tid >> 4)) * N + (tid & 15) * 4);

        As[a_col + 0][a_row] = av.x;
        As[a_col + 1][a_row] = av.y;
        As[a_col + 2][a_row] = av.z;
        As[a_col + 3][a_row] = av.w;
        if (tid < 128)
            *(float4*)&Bs[tid >> 4][(tid & 15) * 4] = bv;
        __syncthreads();

#pragma unroll
        for (int k = 0; k < 8; k++) {
            float a[8], b[4];
            *(float4*)(a)     = *(const float4*)&As[k][ty * 8];
            *(float4*)(a + 4) = *(const float4*)&As[k][ty * 8 + 4];
            *(float4*)(b)     = *(const float4*)&Bs[k][tx * 4];
#pragma unroll
            for (int i = 0; i < 8; i++)
#pragma unroll
                for (int j = 0; j < 4; j++) acc[i][j] += a[i] * b[j];
        }
        __syncthreads();
    }

#pragma unroll
    for (int i = 0; i < 8; i++) {
        int r = brow + ty * 8 + i;
        if (r >= M) break;
        int c = tx * 4;
        float4 v;
        v.x = acc[i][0] + bias[c + 0];
        v.y = acc[i][1] + bias[c + 1];
        v.z = acc[i][2] + bias[c + 2];
        v.w = acc[i][3] + bias[c + 3];
        *(float4*)(g_H + (size_t)r * OUT_DIM + c) = v;   // hop-0 slice
    }
}

// ---------------- CSR build ----------------
__global__ void zero_deg_kernel(int n)
{
    int i = blockIdx.x * blockDim.x + threadIdx.x;
    if (i < n) g_deg[i] = 0;
}

__global__ void hist_kernel(const int* __restrict__ row, int E)
{
    int e = blockIdx.x * blockDim.x + threadIdx.x;
    if (e < E) atomicAdd(&g_deg[row[e]], 1);
}

__global__ __launch_bounds__(1024) void scan_kernel(int n)
{
    __shared__ int sums[1024];
    int tid = threadIdx.x;
    int per = (n + 1023) >> 10;
    int start = tid * per;
    int end = min(start + per, n);

    int s = 0;
    for (int i = start; i < end; ++i) s += g_deg[i];
    sums[tid] = s;
    __syncthreads();

    for (int off = 1; off < 1024; off <<= 1) {
        int v = 0;
        if (tid >= off) v = sums[tid - off];
        __syncthreads();
        sums[tid] += v;
        __syncthreads();
    }

    int run = sums[tid] - s;  // exclusive base for this thread
    for (int i = start; i < end; ++i) {
        g_rowptr[i] = run;
        g_cursor[i] = run;
        run += g_deg[i];
    }
    if (tid == 1023) g_rowptr[n] = sums[1023];
}

__global__ void scatter_kernel(const int* __restrict__ row, const int* __restrict__ col,
                               const float* __restrict__ w, int E)
{
    int e = blockIdx.x * blockDim.x + threadIdx.x;
    if (e >= E) return;
    int r = row[e];
    int pos = atomicAdd(&g_cursor[r], 1);
    g_scol[pos] = col[e];
    g_sw[pos]  = w[e];
}

// ---------------- SpMM hop: H[hop] = A_norm @ H[hop-1], warp per row ----------------
__global__ __launch_bounds__(256) void spmm_kernel(int hop, int n)
{
    int warp = (blockIdx.x * blockDim.x + threadIdx.x) >> 5;
    int lane = threadIdx.x & 31;
    if (warp >= n) return;

    const float2* __restrict__ hin =
        (const float2*)(g_H + (size_t)(hop - 1) * N_NODES * OUT_DIM);
    float2* __restrict__ hout =
        (float2*)(g_H + (size_t)hop * N_NODES * OUT_DIM);

    int s  = g_rowptr[warp];
    int e2 = g_rowptr[warp + 1];

    float ax = 0.f, ay = 0.f;
    int i = s;
    for (; i + 1 < e2; i += 2) {
        int   c0 = g_scol[i],   c1 = g_scol[i + 1];
        float w0 = g_sw[i],     w1 = g_sw[i + 1];
        float2 v0 = hin[(size_t)c0 * 32 + lane];
        float2 v1 = hin[(size_t)c1 * 32 + lane];
        ax += w0 * v0.x; ay += w0 * v0.y;
        ax += w1 * v1.x; ay += w1 * v1.y;
    }
    if (i < e2) {
        int   c0 = g_scol[i];
        float w0 = g_sw[i];
        float2 v0 = hin[(size_t)c0 * 32 + lane];
        ax += w0 * v0.x; ay += w0 * v0.y;
    }
    hout[(size_t)warp * 32 + lane] = make_float2(ax, ay);
}

// ---------------- Combine: out[n] = sum_k sigmoid(H[n,k]·s) * H[n,k,:] ----------------
__global__ __launch_bounds__(256) void combine_kernel(
    const float* __restrict__ s, float* __restrict__ out, int n)
{
    int warp = (blockIdx.x * blockDim.x + threadIdx.x) >> 5;
    int lane = threadIdx.x & 31;
    if (warp >= n) return;

    float s0 = s[lane * 2 + 0];
    float s1 = s[lane * 2 + 1];

    float ox = 0.f, oy = 0.f;
#pragma unroll
    for (int k = 0; k <= HOPS; k++) {
        const float2* hk = (const float2*)(g_H + (size_t)k * N_NODES * OUT_DIM);
        float2 h = hk[(size_t)warp * 32 + lane];
        float d = h.x * s0 + h.y * s1;
#pragma unroll
        for (int off = 16; off; off >>= 1) d += __shfl_xor_sync(0xffffffffu, d, off);
        float sg = 1.f / (1.f + expf(-d));
        ox += sg * h.x;
        oy += sg * h.y;
    }
    ((float2*)out)[(size_t)warp * 32 + lane] = make_float2(ox, oy);
}

// ---------------- launch ----------------
extern "C" void kernel_launch(void* const* d_in, const int* in_sizes, int n_in,
                              void* d_out, int out_size)
{
    const float* x   = (const float*)d_in[0];
    const int*   row = (const int*)  d_in[1];
    const int*   col = (const int*)  d_in[2];
    const float* ew  = (const float*)d_in[3];
    const float* W1  = (const float*)d_in[4];
    const float* b1  = (const float*)d_in[5];
    const float* W2  = (const float*)d_in[6];
    const float* b2  = (const float*)d_in[7];
    const float* s   = (const float*)d_in[8];

    int M = in_sizes[0] / IN_DIM;  // 100000
    int E = in_sizes[1];           // 3300000

    // dense front-end
    dim3 g1((M + 127) / 128, HID_DIM / 128);
    gemm1_relu_kernel<<<g1, 256>>>(x, W1, b1, M);
    gemm2_kernel<<<(M + 127) / 128, 256>>>(W2, b2, M);

    // CSR build (per call; graph-capturable kernels only)
    zero_deg_kernel<<<(M + 255) / 256, 256>>>(M);
    hist_kernel<<<(E + 255) / 256, 256>>>(row, E);
    scan_kernel<<<1, 1024>>>(M);
    scatter_kernel<<<(E + 255) / 256, 256>>>(row, col, ew, E);

    // 10 propagation hops
    int spmm_blocks = (M * 32 + 255) / 256;
    for (int hop = 1; hop <= HOPS; ++hop)
        spmm_kernel<<<spmm_blocks, 256>>>(hop, M);

    // gated combine
    combine_kernel<<<spmm_blocks, 256>>>(s, (float*)d_out, M);
}

// round 3
// speedup vs baseline: 1.3619x; 1.3619x over previous
#include <cuda_runtime.h>
#include <cuda_bf16.h>
#include <math.h>
#include <stdint.h>

#define N_NODES 100000
#define E_MAX   3300000
#define IN_DIM  512
#define HID_DIM 512
#define OUT_DIM 64
#define HOPS    10

// ---------------- scratch (static device globals; no allocations) ----------------
__device__ float g_h1[(size_t)N_NODES * HID_DIM];                 // 204.8 MB
__device__ float g_H[(size_t)(HOPS + 1) * N_NODES * OUT_DIM];     // 281.6 MB
__device__ int   g_deg[N_NODES];
__device__ int   g_rowptr[N_NODES + 1];
__device__ int   g_cursor[N_NODES];
__device__ int   g_scol[E_MAX];
__device__ float g_sw[E_MAX];
// split-bf16 operands for tensor-core GEMM1
__device__ __nv_bfloat16 g_xhi[(size_t)N_NODES * IN_DIM];         // 102.4 MB
__device__ __nv_bfloat16 g_xlo[(size_t)N_NODES * IN_DIM];         // 102.4 MB
__device__ __nv_bfloat16 g_w1t_hi[(size_t)HID_DIM * IN_DIM];      // 0.5 MB ([n][k])
__device__ __nv_bfloat16 g_w1t_lo[(size_t)HID_DIM * IN_DIM];      // 0.5 MB

// ================= PTX helpers (baseline ISA: mma.sync / ldmatrix / cp.async) =====
__device__ __forceinline__ uint32_t smem_u32(const void* p) {
    uint32_t a;
    asm("{ .reg .u64 t; cvta.to.shared.u64 t, %1; cvt.u32.u64 %0, t; }" : "=r"(a) : "l"(p));
    return a;
}
__device__ __forceinline__ void cp_async16(uint32_t s, const void* g, int sz) {
    asm volatile("cp.async.cg.shared.global [%0], [%1], 16, %2;"
                 :: "r"(s), "l"(g), "r"(sz) : "memory");
}
__device__ __forceinline__ void cp_commit() {
    asm volatile("cp.async.commit_group;" ::: "memory");
}
template <int N>
__device__ __forceinline__ void cp_wait() {
    asm volatile("cp.async.wait_group %0;" :: "n"(N) : "memory");
}
__device__ __forceinline__ void ldsm_x4(uint32_t* r, uint32_t addr) {
    asm volatile("ldmatrix.sync.aligned.m8n8.x4.shared.b16 {%0,%1,%2,%3}, [%4];"
                 : "=r"(r[0]), "=r"(r[1]), "=r"(r[2]), "=r"(r[3]) : "r"(addr));
}
__device__ __forceinline__ void mma_bf16(float* d, const uint32_t* a, const uint32_t* b) {
    asm volatile(
        "mma.sync.aligned.m16n8k16.row.col.f32.bf16.bf16.f32 "
        "{%0,%1,%2,%3}, {%4,%5,%6,%7}, {%8,%9}, {%0,%1,%2,%3};"
        : "+f"(d[0]), "+f"(d[1]), "+f"(d[2]), "+f"(d[3])
        : "r"(a[0]), "r"(a[1]), "r"(a[2]), "r"(a[3]), "r"(b[0]), "r"(b[1]));
}

// ---------------- split-bf16 conversion kernels ----------------
__global__ void conv_x_kernel(const float* __restrict__ x, size_t n4)
{
    size_t i = (size_t)blockIdx.x * blockDim.x + threadIdx.x;
    if (i >= n4) return;
    float4 v = *(const float4*)(x + i * 4);
    union { __nv_bfloat16 h[4]; uint2 u; } hi, lo;
    float f[4] = {v.x, v.y, v.z, v.w};
#pragma unroll
    for (int j = 0; j < 4; j++) {
        __nv_bfloat16 h = __float2bfloat16_rn(f[j]);
        hi.h[j] = h;
        lo.h[j] = __float2bfloat16_rn(f[j] - __bfloat162float(h));
    }
    *(uint2*)(g_xhi + i * 4) = hi.u;
    *(uint2*)(g_xlo + i * 4) = lo.u;
}

__global__ void conv_w1_kernel(const float* __restrict__ W1)
{
    int i = blockIdx.x * blockDim.x + threadIdx.x;  // i = n*512 + k
    if (i >= HID_DIM * IN_DIM) return;
    int n = i >> 9, k = i & 511;
    float v = W1[k * HID_DIM + n];
    __nv_bfloat16 h = __float2bfloat16_rn(v);
    g_w1t_hi[i] = h;
    g_w1t_lo[i] = __float2bfloat16_rn(v - __bfloat162float(h));
}

// ---------------- GEMM1 (mma.sync bf16 split-3): h1 = relu(x @ W1 + b1) --------
// CTA 128x128, 8 warps (4M x 2N), warp tile 32x64. K chunks of 32, double buffered.
#define G1_NKC   (IN_DIM / 32)      // 16 chunks
#define G1_PITCH 80                 // bytes per smem row (40 bf16, conflict-free)
#define G1_TILE  (128 * G1_PITCH)   // 10240 B
#define G1_STAGE (4 * G1_TILE)      // A_hi, A_lo, B_hi, B_lo = 40960 B
#define G1_SMEM  (2 * G1_STAGE)     // 81920 B

__global__ __launch_bounds__(256) void gemm1_mma_kernel(const float* __restrict__ bias, int M)
{
    extern __shared__ char smem[];
    const int tid  = threadIdx.x;
    const int wid  = tid >> 5, lane = tid & 31;
    const int wm   = wid & 3,  wn   = wid >> 2;
    const int brow = blockIdx.x * 128, bcol = blockIdx.y * 128;

    const uint32_t sbase = smem_u32(smem);
    const uint32_t AHI = 0, ALO = G1_TILE, BHI = 2 * G1_TILE, BLO = 3 * G1_TILE;

    float d[2][8][4];
#pragma unroll
    for (int i = 0; i < 2; i++)
#pragma unroll
        for (int j = 0; j < 8; j++)
#pragma unroll
            for (int k = 0; k < 4; k++) d[i][j][k] = 0.f;

    // ---- async chunk loader: 512 16B-segments per tile; 2 per thread per tile
    auto issue_load = [&](int kc, int st) {
        const int k0 = kc * 32;
        const uint32_t s0 = sbase + st * G1_STAGE;
#pragma unroll
        for (int i = 0; i < 2; i++) {
            int seg = tid + i * 256;
            int row = seg >> 2, sc = seg & 3;
            uint32_t soff = row * G1_PITCH + sc * 16;
            int ar = brow + row;
            int ok = (ar < M);
            size_t gA = (size_t)(ok ? ar : 0) * IN_DIM + k0 + sc * 8;
            int sz = ok ? 16 : 0;
            cp_async16(s0 + AHI + soff, g_xhi + gA, sz);
            cp_async16(s0 + ALO + soff, g_xlo + gA, sz);
            size_t gB = (size_t)(bcol + row) * IN_DIM + k0 + sc * 8;
            cp_async16(s0 + BHI + soff, g_w1t_hi + gB, 16);
            cp_async16(s0 + BLO + soff, g_w1t_lo + gB, 16);
        }
        cp_commit();
    };

    issue_load(0, 0);

    for (int kc = 0; kc < G1_NKC; kc++) {
        const int st = kc & 1;
        if (kc + 1 < G1_NKC) {
            issue_load(kc + 1, st ^ 1);
            cp_wait<1>();
        } else {
            cp_wait<0>();
        }
        __syncthreads();

        const uint32_t s0 = sbase + st * G1_STAGE;
#pragma unroll
        for (int ks = 0; ks < 2; ks++) {
            // A fragments: 2 m16 tiles, hi & lo
            uint32_t ahi[2][4], alo[2][4];
            const int ac = (ks * 16 + (lane >> 4) * 8) * 2;  // byte col
#pragma unroll
            for (int mt = 0; mt < 2; mt++) {
                int r = wm * 32 + mt * 16 + (lane & 15);
                ldsm_x4(ahi[mt], s0 + AHI + r * G1_PITCH + ac);
                ldsm_x4(alo[mt], s0 + ALO + r * G1_PITCH + ac);
            }
            // B fragments: pairs of n8 tiles
            const int bn_l = (lane >> 4) * 8 + (lane & 7);
            const int bk   = (ks * 16 + ((lane >> 3) & 1) * 8) * 2;
#pragma unroll
            for (int p = 0; p < 4; p++) {
                uint32_t bhi[4], blo[4];
                int n = wn * 64 + p * 16 + bn_l;
                ldsm_x4(bhi, s0 + BHI + n * G1_PITCH + bk);
                ldsm_x4(blo, s0 + BLO + n * G1_PITCH + bk);
#pragma unroll
                for (int mt = 0; mt < 2; mt++) {
#pragma unroll
                    for (int j = 0; j < 2; j++) {
                        float* acc = d[mt][2 * p + j];
                        mma_bf16(acc, ahi[mt], bhi + 2 * j);
                        mma_bf16(acc, ahi[mt], blo + 2 * j);
                        mma_bf16(acc, alo[mt], bhi + 2 * j);
                    }
                }
            }
        }
        __syncthreads();
    }

    // ---- epilogue: bias + relu, write fp32 h1
#pragma unroll
    for (int mt = 0; mt < 2; mt++) {
        int row0 = brow + wm * 32 + mt * 16 + (lane >> 2);
#pragma unroll
        for (int nt = 0; nt < 8; nt++) {
            int col = bcol + wn * 64 + nt * 8 + (lane & 3) * 2;
            float b0 = bias[col], b1 = bias[col + 1];
            if (row0 < M) {
                float2 v0 = make_float2(fmaxf(d[mt][nt][0] + b0, 0.f),
                                        fmaxf(d[mt][nt][1] + b1, 0.f));
                *(float2*)(g_h1 + (size_t)row0 * HID_DIM + col) = v0;
            }
            int row1 = row0 + 8;
            if (row1 < M) {
                float2 v1 = make_float2(fmaxf(d[mt][nt][2] + b0, 0.f),
                                        fmaxf(d[mt][nt][3] + b1, 0.f));
                *(float2*)(g_h1 + (size_t)row1 * HID_DIM + col) = v1;
            }
        }
    }
}

// ---------------- GEMM2: H0 = h1 @ W2 + b2, [M,512]x[512,64] (FFMA) ----------------
__global__ __launch_bounds__(256) void gemm2_kernel(
    const float* __restrict__ B, const float* __restrict__ bias, int M)
{
    const int K = HID_DIM, N = OUT_DIM;
    __shared__ float As[8][128];
    __shared__ float Bs[8][64];

    int tid  = threadIdx.x;
    int brow = blockIdx.x * 128;

    int a_row = tid >> 1;
    int a_col = (tid & 1) * 4;
    int ty = tid >> 4;
    int tx = tid & 15;

    float acc[8][4];
#pragma unroll
    for (int i = 0; i < 8; i++)
#pragma unroll
        for (int j = 0; j < 4; j++) acc[i][j] = 0.f;

    bool a_ok = (brow + a_row) < M;
    const float* Aptr = g_h1 + (size_t)(brow + a_row) * K + a_col;

    for (int kt = 0; kt < K; kt += 8) {
        float4 av = a_ok ? *(const float4*)(Aptr + kt) : make_float4(0.f, 0.f, 0.f, 0.f);
        float4 bv = make_float4(0.f, 0.f, 0.f, 0.f);
        if (tid < 128)
            bv = *(const float4*)(B + (size_t)(kt + (tid >> 4)) * N + (tid & 15) * 4);

        As[a_col + 0][a_row] = av.x;
        As[a_col + 1][a_row] = av.y;
        As[a_col + 2][a_row] = av.z;
        As[a_col + 3][a_row] = av.w;
        if (tid < 128)
            *(float4*)&Bs[tid >> 4][(tid & 15) * 4] = bv;
        __syncthreads();

#pragma unroll
        for (int k = 0; k < 8; k++) {
            float a[8], b[4];
            *(float4*)(a)     = *(const float4*)&As[k][ty * 8];
            *(float4*)(a + 4) = *(const float4*)&As[k][ty * 8 + 4];
            *(float4*)(b)     = *(const float4*)&Bs[k][tx * 4];
#pragma unroll
            for (int i = 0; i < 8; i++)
#pragma unroll
                for (int j = 0; j < 4; j++) acc[i][j] += a[i] * b[j];
        }
        __syncthreads();
    }

#pragma unroll
    for (int i = 0; i < 8; i++) {
        int r = brow + ty * 8 + i;
        if (r >= M) break;
        int c = tx * 4;
        float4 v;
        v.x = acc[i][0] + bias[c + 0];
        v.y = acc[i][1] + bias[c + 1];
        v.z = acc[i][2] + bias[c + 2];
        v.w = acc[i][3] + bias[c + 3];
        *(float4*)(g_H + (size_t)r * OUT_DIM + c) = v;
    }
}

// ---------------- CSR build ----------------
__global__ void zero_deg_kernel(int n)
{
    int i = blockIdx.x * blockDim.x + threadIdx.x;
    if (i < n) g_deg[i] = 0;
}

__global__ void hist_kernel(const int* __restrict__ row, int E)
{
    int e = blockIdx.x * blockDim.x + threadIdx.x;
    if (e < E) atomicAdd(&g_deg[row[e]], 1);
}

__global__ __launch_bounds__(1024) void scan_kernel(int n)
{
    __shared__ int sums[1024];
    int tid = threadIdx.x;
    int per = (n + 1023) >> 10;
    int start = tid * per;
    int end = min(start + per, n);

    int s = 0;
    for (int i = start; i < end; ++i) s += g_deg[i];
    sums[tid] = s;
    __syncthreads();

    for (int off = 1; off < 1024; off <<= 1) {
        int v = 0;
        if (tid >= off) v = sums[tid - off];
        __syncthreads();
        sums[tid] += v;
        __syncthreads();
    }

    int run = sums[tid] - s;
    for (int i = start; i < end; ++i) {
        g_rowptr[i] = run;
        g_cursor[i] = run;
        run += g_deg[i];
    }
    if (tid == 1023) g_rowptr[n] = sums[1023];
}

__global__ void scatter_kernel(const int* __restrict__ row, const int* __restrict__ col,
                               const float* __restrict__ w, int E)
{
    int e = blockIdx.x * blockDim.x + threadIdx.x;
    if (e >= E) return;
    int r = row[e];
    int pos = atomicAdd(&g_cursor[r], 1);
    g_scol[pos] = col[e];
    g_sw[pos]  = w[e];
}

// ---------------- SpMM hop ----------------
__global__ __launch_bounds__(256) void spmm_kernel(int hop, int n)
{
    int warp = (blockIdx.x * blockDim.x + threadIdx.x) >> 5;
    int lane = threadIdx.x & 31;
    if (warp >= n) return;

    const float2* __restrict__ hin =
        (const float2*)(g_H + (size_t)(hop - 1) * N_NODES * OUT_DIM);
    float2* __restrict__ hout =
        (float2*)(g_H + (size_t)hop * N_NODES * OUT_DIM);

    int s  = g_rowptr[warp];
    int e2 = g_rowptr[warp + 1];

    float ax = 0.f, ay = 0.f;
    int i = s;
    for (; i + 1 < e2; i += 2) {
        int   c0 = g_scol[i],   c1 = g_scol[i + 1];
        float w0 = g_sw[i],     w1 = g_sw[i + 1];
        float2 v0 = hin[(size_t)c0 * 32 + lane];
        float2 v1 = hin[(size_t)c1 * 32 + lane];
        ax += w0 * v0.x; ay += w0 * v0.y;
        ax += w1 * v1.x; ay += w1 * v1.y;
    }
    if (i < e2) {
        int   c0 = g_scol[i];
        float w0 = g_sw[i];
        float2 v0 = hin[(size_t)c0 * 32 + lane];
        ax += w0 * v0.x; ay += w0 * v0.y;
    }
    hout[(size_t)warp * 32 + lane] = make_float2(ax, ay);
}

// ---------------- Combine ----------------
__global__ __launch_bounds__(256) void combine_kernel(
    const float* __restrict__ s, float* __restrict__ out, int n)
{
    int warp = (blockIdx.x * blockDim.x + threadIdx.x) >> 5;
    int lane = threadIdx.x & 31;
    if (warp >= n) return;

    float s0 = s[lane * 2 + 0];
    float s1 = s[lane * 2 + 1];

    float ox = 0.f, oy = 0.f;
#pragma unroll
    for (int k = 0; k <= HOPS; k++) {
        const float2* hk = (const float2*)(g_H + (size_t)k * N_NODES * OUT_DIM);
        float2 h = hk[(size_t)warp * 32 + lane];
        float d = h.x * s0 + h.y * s1;
#pragma unroll
        for (int off = 16; off; off >>= 1) d += __shfl_xor_sync(0xffffffffu, d, off);
        float sg = 1.f / (1.f + expf(-d));
        ox += sg * h.x;
        oy += sg * h.y;
    }
    ((float2*)out)[(size_t)warp * 32 + lane] = make_float2(ox, oy);
}

// ---------------- launch ----------------
extern "C" void kernel_launch(void* const* d_in, const int* in_sizes, int n_in,
                              void* d_out, int out_size)
{
    const float* x   = (const float*)d_in[0];
    const int*   row = (const int*)  d_in[1];
    const int*   col = (const int*)  d_in[2];
    const float* ew  = (const float*)d_in[3];
    const float* W1  = (const float*)d_in[4];
    const float* b1  = (const float*)d_in[5];
    const float* W2  = (const float*)d_in[6];
    const float* b2  = (const float*)d_in[7];
    const float* s   = (const float*)d_in[8];

    int M = in_sizes[0] / IN_DIM;  // 100000
    int E = in_sizes[1];           // 3300000

    // split-bf16 conversion
    size_t n4 = (size_t)M * IN_DIM / 4;
    conv_x_kernel<<<(unsigned)((n4 + 255) / 256), 256>>>(x, n4);
    conv_w1_kernel<<<(HID_DIM * IN_DIM + 255) / 256, 256>>>(W1);

    // GEMM1 on tensor cores via mma.sync
    static bool attr_set = false;
    if (!attr_set) {
        cudaFuncSetAttribute(gemm1_mma_kernel,
                             cudaFuncAttributeMaxDynamicSharedMemorySize, G1_SMEM);
        attr_set = true;
    }
    dim3 g1((M + 127) / 128, HID_DIM / 128);
    gemm1_mma_kernel<<<g1, 256, G1_SMEM>>>(b1, M);

    gemm2_kernel<<<(M + 127) / 128, 256>>>(W2, b2, M);

    // CSR build
    zero_deg_kernel<<<(M + 255) / 256, 256>>>(M);
    hist_kernel<<<(E + 255) / 256, 256>>>(row, E);
    scan_kernel<<<1, 1024>>>(M);
    scatter_kernel<<<(E + 255) / 256, 256>>>(row, col, ew, E);

    // 10 propagation hops
    int spmm_blocks = (M * 32 + 255) / 256;
    for (int hop = 1; hop <= HOPS; ++hop)
        spmm_kernel<<<spmm_blocks, 256>>>(hop, M);

    // gated combine
    combine_kernel<<<spmm_blocks, 256>>>(s, (float*)d_out, M);
}

// round 4
// speedup vs baseline: 1.5135x; 1.1113x over previous
#include <cuda_runtime.h>
#include <cuda_bf16.h>
#include <cuda_fp16.h>
#include <math.h>
#include <stdint.h>

#define N_NODES 100000
#define E_MAX   3300000
#define IN_DIM  512
#define HID_DIM 512
#define OUT_DIM 64
#define HOPS    10

// ---------------- scratch (static device globals; no allocations) ----------------
__device__ __nv_bfloat16 g_h1hi[(size_t)N_NODES * HID_DIM];       // 102.4 MB
__device__ __nv_bfloat16 g_h1lo[(size_t)N_NODES * HID_DIM];       // 102.4 MB
__device__ __half g_Hh[(size_t)(HOPS + 1) * N_NODES * OUT_DIM];   // 140.8 MB
__device__ int   g_deg[N_NODES];
__device__ int   g_rowptr[N_NODES + 1];
__device__ int   g_cursor[N_NODES];
__device__ int2  g_edge[E_MAX];                                   // (col, w bits)
// split-bf16 operands
__device__ __nv_bfloat16 g_xhi[(size_t)N_NODES * IN_DIM];         // 102.4 MB
__device__ __nv_bfloat16 g_xlo[(size_t)N_NODES * IN_DIM];         // 102.4 MB
__device__ __nv_bfloat16 g_w1t_hi[(size_t)HID_DIM * IN_DIM];      // 0.5 MB ([n][k])
__device__ __nv_bfloat16 g_w1t_lo[(size_t)HID_DIM * IN_DIM];
__device__ __nv_bfloat16 g_w2t_hi[(size_t)OUT_DIM * HID_DIM];     // 64 KB ([n][k])
__device__ __nv_bfloat16 g_w2t_lo[(size_t)OUT_DIM * HID_DIM];

// ================= PTX helpers =================
__device__ __forceinline__ uint32_t smem_u32(const void* p) {
    uint32_t a;
    asm("{ .reg .u64 t; cvta.to.shared.u64 t, %1; cvt.u32.u64 %0, t; }" : "=r"(a) : "l"(p));
    return a;
}
__device__ __forceinline__ void cp_async16(uint32_t s, const void* g, int sz) {
    asm volatile("cp.async.cg.shared.global [%0], [%1], 16, %2;"
                 :: "r"(s), "l"(g), "r"(sz) : "memory");
}
__device__ __forceinline__ void cp_commit() {
    asm volatile("cp.async.commit_group;" ::: "memory");
}
template <int N>
__device__ __forceinline__ void cp_wait() {
    asm volatile("cp.async.wait_group %0;" :: "n"(N) : "memory");
}
__device__ __forceinline__ void ldsm_x4(uint32_t* r, uint32_t addr) {
    asm volatile("ldmatrix.sync.aligned.m8n8.x4.shared.b16 {%0,%1,%2,%3}, [%4];"
                 : "=r"(r[0]), "=r"(r[1]), "=r"(r[2]), "=r"(r[3]) : "r"(addr));
}
__device__ __forceinline__ void mma_bf16(float* d, const uint32_t* a, const uint32_t* b) {
    asm volatile(
        "mma.sync.aligned.m16n8k16.row.col.f32.bf16.bf16.f32 "
        "{%0,%1,%2,%3}, {%4,%5,%6,%7}, {%8,%9}, {%0,%1,%2,%3};"
        : "+f"(d[0]), "+f"(d[1]), "+f"(d[2]), "+f"(d[3])
        : "r"(a[0]), "r"(a[1]), "r"(a[2]), "r"(a[3]), "r"(b[0]), "r"(b[1]));
}

// ---------------- split-bf16 conversion kernels ----------------
__global__ void conv_x_kernel(const float* __restrict__ x, size_t n4)
{
    size_t i = (size_t)blockIdx.x * blockDim.x + threadIdx.x;
    if (i >= n4) return;
    float4 v = *(const float4*)(x + i * 4);
    union { __nv_bfloat16 h[4]; uint2 u; } hi, lo;
    float f[4] = {v.x, v.y, v.z, v.w};
#pragma unroll
    for (int j = 0; j < 4; j++) {
        __nv_bfloat16 h = __float2bfloat16_rn(f[j]);
        hi.h[j] = h;
        lo.h[j] = __float2bfloat16_rn(f[j] - __bfloat162float(h));
    }
    *(uint2*)(g_xhi + i * 4) = hi.u;
    *(uint2*)(g_xlo + i * 4) = lo.u;
}

__global__ void conv_w1_kernel(const float* __restrict__ W1)
{
    int i = blockIdx.x * blockDim.x + threadIdx.x;  // i = n*512 + k
    if (i >= HID_DIM * IN_DIM) return;
    int n = i >> 9, k = i & 511;
    float v = W1[k * HID_DIM + n];
    __nv_bfloat16 h = __float2bfloat16_rn(v);
    g_w1t_hi[i] = h;
    g_w1t_lo[i] = __float2bfloat16_rn(v - __bfloat162float(h));
}

__global__ void conv_w2_kernel(const float* __restrict__ W2)
{
    int i = blockIdx.x * blockDim.x + threadIdx.x;  // i = n*512 + k
    if (i >= OUT_DIM * HID_DIM) return;
    int n = i >> 9, k = i & 511;
    float v = W2[k * OUT_DIM + n];
    __nv_bfloat16 h = __float2bfloat16_rn(v);
    g_w2t_hi[i] = h;
    g_w2t_lo[i] = __float2bfloat16_rn(v - __bfloat162float(h));
}

// ============ GEMM1 (mma.sync split-3): h1 = relu(x @ W1 + b1) -> bf16 hi/lo ======
// CTA 128x256, 16 warps (4M x 4N), warp tile 32x64. K chunks of 32, 3-stage pipeline.
#define G1_NKC   (IN_DIM / 32)        // 16
#define G1_PITCH 80
#define G1_ATILE (128 * G1_PITCH)     // 10240
#define G1_BTILE (256 * G1_PITCH)     // 20480
#define G1_STAGE (2 * G1_ATILE + 2 * G1_BTILE)  // 61440
#define G1_SMEM  (3 * G1_STAGE)       // 184320

__global__ __launch_bounds__(512, 1) void gemm1_mma_kernel(const float* __restrict__ bias, int M)
{
    extern __shared__ char smem[];
    const int tid  = threadIdx.x;
    const int wid  = tid >> 5, lane = tid & 31;
    const int wm   = wid & 3,  wn   = wid >> 2;      // 4 x 4 warps
    const int brow = blockIdx.x * 128, bcol = blockIdx.y * 256;

    const uint32_t sbase = smem_u32(smem);
    const uint32_t AHI = 0, ALO = G1_ATILE, BHI = 2 * G1_ATILE, BLO = 2 * G1_ATILE + G1_BTILE;

    float d[2][8][4];
#pragma unroll
    for (int i = 0; i < 2; i++)
#pragma unroll
        for (int j = 0; j < 8; j++)
#pragma unroll
            for (int k = 0; k < 4; k++) d[i][j][k] = 0.f;

    auto issue_load = [&](int kc, int st) {
        const int k0 = kc * 32;
        const uint32_t s0 = sbase + st * G1_STAGE;
        {   // A: 512 segs, one per thread
            int row = tid >> 2, sc = tid & 3;
            uint32_t soff = row * G1_PITCH + sc * 16;
            int ar = brow + row;
            int ok = (ar < M);
            size_t gA = (size_t)(ok ? ar : 0) * IN_DIM + k0 + sc * 8;
            int sz = ok ? 16 : 0;
            cp_async16(s0 + AHI + soff, g_xhi + gA, sz);
            cp_async16(s0 + ALO + soff, g_xlo + gA, sz);
        }
#pragma unroll
        for (int i = 0; i < 2; i++) {  // B: 1024 segs
            int seg = tid + i * 512;
            int row = seg >> 2, sc = seg & 3;
            uint32_t soff = row * G1_PITCH + sc * 16;
            size_t gB = (size_t)(bcol + row) * IN_DIM + k0 + sc * 8;
            cp_async16(s0 + BHI + soff, g_w1t_hi + gB, 16);
            cp_async16(s0 + BLO + soff, g_w1t_lo + gB, 16);
        }
        cp_commit();
    };

    issue_load(0, 0);
    issue_load(1, 1);

    for (int kc = 0; kc < G1_NKC; kc++) {
        if (kc == G1_NKC - 1) cp_wait<0>(); else cp_wait<1>();
        __syncthreads();
        if (kc + 2 < G1_NKC) issue_load(kc + 2, (kc + 2) % 3);

        const uint32_t s0 = sbase + (kc % 3) * G1_STAGE;
#pragma unroll
        for (int ks = 0; ks < 2; ks++) {
            uint32_t ahi[2][4], alo[2][4];
            const int ac = (ks * 16 + (lane >> 4) * 8) * 2;
#pragma unroll
            for (int mt = 0; mt < 2; mt++) {
                int r = wm * 32 + mt * 16 + (lane & 15);
                ldsm_x4(ahi[mt], s0 + AHI + r * G1_PITCH + ac);
                ldsm_x4(alo[mt], s0 + ALO + r * G1_PITCH + ac);
            }
            const int bn_l = (lane >> 4) * 8 + (lane & 7);
            const int bk   = (ks * 16 + ((lane >> 3) & 1) * 8) * 2;
#pragma unroll
            for (int p = 0; p < 4; p++) {
                uint32_t bhi[4], blo[4];
                int n = wn * 64 + p * 16 + bn_l;
                ldsm_x4(bhi, s0 + BHI + n * G1_PITCH + bk);
                ldsm_x4(blo, s0 + BLO + n * G1_PITCH + bk);
#pragma unroll
                for (int mt = 0; mt < 2; mt++) {
#pragma unroll
                    for (int j = 0; j < 2; j++) {
                        float* acc = d[mt][2 * p + j];
                        mma_bf16(acc, ahi[mt], bhi + 2 * j);
                        mma_bf16(acc, ahi[mt], blo + 2 * j);
                        mma_bf16(acc, alo[mt], bhi + 2 * j);
                    }
                }
            }
        }
    }

    // ---- epilogue: relu(acc + bias), split to bf16 hi/lo
#pragma unroll
    for (int mt = 0; mt < 2; mt++) {
        int row0 = brow + wm * 32 + mt * 16 + (lane >> 2);
#pragma unroll
        for (int nt = 0; nt < 8; nt++) {
            int col = bcol + wn * 64 + nt * 8 + (lane & 3) * 2;
            float b0 = bias[col], b1 = bias[col + 1];
#pragma unroll
            for (int h = 0; h < 2; h++) {
                int r = row0 + h * 8;
                if (r >= M) continue;
                float v0 = fmaxf(d[mt][nt][2 * h + 0] + b0, 0.f);
                float v1 = fmaxf(d[mt][nt][2 * h + 1] + b1, 0.f);
                __nv_bfloat16 h0 = __float2bfloat16_rn(v0);
                __nv_bfloat16 h1 = __float2bfloat16_rn(v1);
                __nv_bfloat162 hv; hv.x = h0; hv.y = h1;
                __nv_bfloat162 lv;
                lv.x = __float2bfloat16_rn(v0 - __bfloat162float(h0));
                lv.y = __float2bfloat16_rn(v1 - __bfloat162float(h1));
                size_t idx = (size_t)r * HID_DIM + col;
                *(__nv_bfloat162*)(g_h1hi + idx) = hv;
                *(__nv_bfloat162*)(g_h1lo + idx) = lv;
            }
        }
    }
}

// ============ GEMM2 (mma.sync split-3): H0 = h1 @ W2 + b2 -> fp16 ============
// CTA 128x64, 8 warps (4M x 2N), warp tile 32x32. K chunks of 64, 3-stage pipeline.
#define G2_NKC   (HID_DIM / 64)       // 8
#define G2_P     144
#define G2_ATILE (128 * G2_P)         // 18432
#define G2_BTILE (64 * G2_P)          // 9216
#define G2_STAGE (2 * G2_ATILE + 2 * G2_BTILE)  // 55296
#define G2_SMEM  (3 * G2_STAGE)       // 165888

__global__ __launch_bounds__(256, 1) void gemm2_mma_kernel(const float* __restrict__ bias, int M)
{
    extern __shared__ char smem[];
    const int tid  = threadIdx.x;
    const int wid  = tid >> 5, lane = tid & 31;
    const int wm   = wid & 3,  wn   = wid >> 2;      // 4 x 2 warps
    const int brow = blockIdx.x * 128;

    const uint32_t sbase = smem_u32(smem);
    const uint32_t AHI = 0, ALO = G2_ATILE, BHI = 2 * G2_ATILE, BLO = 2 * G2_ATILE + G2_BTILE;

    float d[2][4][4];
#pragma unroll
    for (int i = 0; i < 2; i++)
#pragma unroll
        for (int j = 0; j < 4; j++)
#pragma unroll
            for (int k = 0; k < 4; k++) d[i][j][k] = 0.f;

    auto issue_load = [&](int kc, int st) {
        const int k0 = kc * 64;
        const uint32_t s0 = sbase + st * G2_STAGE;
#pragma unroll
        for (int i = 0; i < 4; i++) {  // A: 1024 segs
            int seg = tid + i * 256;
            int row = seg >> 3, sc = seg & 7;
            uint32_t soff = row * G2_P + sc * 16;
            int ar = brow + row;
            int ok = (ar < M);
            size_t gA = (size_t)(ok ? ar : 0) * HID_DIM + k0 + sc * 8;
            int sz = ok ? 16 : 0;
            cp_async16(s0 + AHI + soff, g_h1hi + gA, sz);
            cp_async16(s0 + ALO + soff, g_h1lo + gA, sz);
        }
#pragma unroll
        for (int i = 0; i < 2; i++) {  // B: 512 segs
            int seg = tid + i * 256;
            int row = seg >> 3, sc = seg & 7;
            uint32_t soff = row * G2_P + sc * 16;
            size_t gB = (size_t)row * HID_DIM + k0 + sc * 8;
            cp_async16(s0 + BHI + soff, g_w2t_hi + gB, 16);
            cp_async16(s0 + BLO + soff, g_w2t_lo + gB, 16);
        }
        cp_commit();
    };

    issue_load(0, 0);
    issue_load(1, 1);

    for (int kc = 0; kc < G2_NKC; kc++) {
        if (kc == G2_NKC - 1) cp_wait<0>(); else cp_wait<1>();
        __syncthreads();
        if (kc + 2 < G2_NKC) issue_load(kc + 2, (kc + 2) % 3);

        const uint32_t s0 = sbase + (kc % 3) * G2_STAGE;
#pragma unroll
        for (int ks = 0; ks < 4; ks++) {
            uint32_t ahi[2][4], alo[2][4];
            const int ac = (ks * 16 + (lane >> 4) * 8) * 2;
#pragma unroll
            for (int mt = 0; mt < 2; mt++) {
                int r = wm * 32 + mt * 16 + (lane & 15);
                ldsm_x4(ahi[mt], s0 + AHI + r * G2_P + ac);
                ldsm_x4(alo[mt], s0 + ALO + r * G2_P + ac);
            }
            const int bn_l = (lane >> 4) * 8 + (lane & 7);
            const int bk   = (ks * 16 + ((lane >> 3) & 1) * 8) * 2;
#pragma unroll
            for (int p = 0; p < 2; p++) {
                uint32_t bhi[4], blo[4];
                int n = wn * 32 + p * 16 + bn_l;
                ldsm_x4(bhi, s0 + BHI + n * G2_P + bk);
                ldsm_x4(blo, s0 + BLO + n * G2_P + bk);
#pragma unroll
                for (int mt = 0; mt < 2; mt++) {
#pragma unroll
                    for (int j = 0; j < 2; j++) {
                        float* acc = d[mt][2 * p + j];
                        mma_bf16(acc, ahi[mt], bhi + 2 * j);
                        mma_bf16(acc, ahi[mt], blo + 2 * j);
                        mma_bf16(acc, alo[mt], bhi + 2 * j);
                    }
                }
            }
        }
    }

    // ---- epilogue: + bias, write fp16 H0
#pragma unroll
    for (int mt = 0; mt < 2; mt++) {
        int row0 = brow + wm * 32 + mt * 16 + (lane >> 2);
#pragma unroll
        for (int nt = 0; nt < 4; nt++) {
            int col = wn * 32 + nt * 8 + (lane & 3) * 2;
            float b0 = bias[col], b1 = bias[col + 1];
#pragma unroll
            for (int h = 0; h < 2; h++) {
                int r = row0 + h * 8;
                if (r >= M) continue;
                __half2 hv = __floats2half2_rn(d[mt][nt][2 * h + 0] + b0,
                                               d[mt][nt][2 * h + 1] + b1);
                *(__half2*)(g_Hh + (size_t)r * OUT_DIM + col) = hv;
            }
        }
    }
}

// ---------------- CSR build ----------------
__global__ void zero_deg_kernel(int n)
{
    int i = blockIdx.x * blockDim.x + threadIdx.x;
    if (i < n) g_deg[i] = 0;
}

__global__ void hist_kernel(const int* __restrict__ row, int E)
{
    int e = blockIdx.x * blockDim.x + threadIdx.x;
    if (e < E) atomicAdd(&g_deg[row[e]], 1);
}

__global__ __launch_bounds__(1024) void scan_kernel(int n)
{
    __shared__ int sums[1024];
    int tid = threadIdx.x;
    int per = (n + 1023) >> 10;
    int start = tid * per;
    int end = min(start + per, n);

    int s = 0;
    for (int i = start; i < end; ++i) s += g_deg[i];
    sums[tid] = s;
    __syncthreads();

    for (int off = 1; off < 1024; off <<= 1) {
        int v = 0;
        if (tid >= off) v = sums[tid - off];
        __syncthreads();
        sums[tid] += v;
        __syncthreads();
    }

    int run = sums[tid] - s;
    for (int i = start; i < end; ++i) {
        g_rowptr[i] = run;
        g_cursor[i] = run;
        run += g_deg[i];
    }
    if (tid == 1023) g_rowptr[n] = sums[1023];
}

__global__ void scatter_kernel(const int* __restrict__ row, const int* __restrict__ col,
                               const float* __restrict__ w, int E)
{
    int e = blockIdx.x * blockDim.x + threadIdx.x;
    if (e >= E) return;
    int r = row[e];
    int pos = atomicAdd(&g_cursor[r], 1);
    g_edge[pos] = make_int2(col[e], __float_as_int(w[e]));
}

// ---------------- SpMM hop (fp16 features): H[hop] = A @ H[hop-1] ----------------
__global__ __launch_bounds__(256) void spmm_kernel(int hop, int n)
{
    int warp = (blockIdx.x * blockDim.x + threadIdx.x) >> 5;
    int lane = threadIdx.x & 31;
    if (warp >= n) return;

    const __half2* __restrict__ hin =
        (const __half2*)(g_Hh + (size_t)(hop - 1) * N_NODES * OUT_DIM);
    __half2* __restrict__ hout =
        (__half2*)(g_Hh + (size_t)hop * N_NODES * OUT_DIM);

    int s  = g_rowptr[warp];
    int e2 = g_rowptr[warp + 1];

    float ax = 0.f, ay = 0.f;
    int i = s;
    for (; i + 1 < e2; i += 2) {
        int2 e0 = g_edge[i], e1 = g_edge[i + 1];
        float w0 = __int_as_float(e0.y), w1 = __int_as_float(e1.y);
        float2 v0 = __half22float2(hin[(size_t)e0.x * 32 + lane]);
        float2 v1 = __half22float2(hin[(size_t)e1.x * 32 + lane]);
        ax += w0 * v0.x; ay += w0 * v0.y;
        ax += w1 * v1.x; ay += w1 * v1.y;
    }
    if (i < e2) {
        int2 e0 = g_edge[i];
        float w0 = __int_as_float(e0.y);
        float2 v0 = __half22float2(hin[(size_t)e0.x * 32 + lane]);
        ax += w0 * v0.x; ay += w0 * v0.y;
    }
    hout[(size_t)warp * 32 + lane] = __floats2half2_rn(ax, ay);
}

// ---------------- Combine ----------------
__global__ __launch_bounds__(256) void combine_kernel(
    const float* __restrict__ s, float* __restrict__ out, int n)
{
    int warp = (blockIdx.x * blockDim.x + threadIdx.x) >> 5;
    int lane = threadIdx.x & 31;
    if (warp >= n) return;

    float s0 = s[lane * 2 + 0];
    float s1 = s[lane * 2 + 1];

    float ox = 0.f, oy = 0.f;
#pragma unroll
    for (int k = 0; k <= HOPS; k++) {
        const __half2* hk = (const __half2*)(g_Hh + (size_t)k * N_NODES * OUT_DIM);
        float2 h = __half22float2(hk[(size_t)warp * 32 + lane]);
        float d = h.x * s0 + h.y * s1;
#pragma unroll
        for (int off = 16; off; off >>= 1) d += __shfl_xor_sync(0xffffffffu, d, off);
        float sg = 1.f / (1.f + expf(-d));
        ox += sg * h.x;
        oy += sg * h.y;
    }
    ((float2*)out)[(size_t)warp * 32 + lane] = make_float2(ox, oy);
}

// ---------------- launch ----------------
extern "C" void kernel_launch(void* const* d_in, const int* in_sizes, int n_in,
                              void* d_out, int out_size)
{
    const float* x   = (const float*)d_in[0];
    const int*   row = (const int*)  d_in[1];
    const int*   col = (const int*)  d_in[2];
    const float* ew  = (const float*)d_in[3];
    const float* W1  = (const float*)d_in[4];
    const float* b1  = (const float*)d_in[5];
    const float* W2  = (const float*)d_in[6];
    const float* b2  = (const float*)d_in[7];
    const float* s   = (const float*)d_in[8];

    int M = in_sizes[0] / IN_DIM;  // 100000
    int E = in_sizes[1];           // 3300000

    static bool attr_set = false;
    if (!attr_set) {
        cudaFuncSetAttribute(gemm1_mma_kernel,
                             cudaFuncAttributeMaxDynamicSharedMemorySize, G1_SMEM);
        cudaFuncSetAttribute(gemm2_mma_kernel,
                             cudaFuncAttributeMaxDynamicSharedMemorySize, G2_SMEM);
        attr_set = true;
    }

    // split-bf16 conversion
    size_t n4 = (size_t)M * IN_DIM / 4;
    conv_x_kernel<<<(unsigned)((n4 + 255) / 256), 256>>>(x, n4);
    conv_w1_kernel<<<(HID_DIM * IN_DIM + 255) / 256, 256>>>(W1);
    conv_w2_kernel<<<(OUT_DIM * HID_DIM + 255) / 256, 256>>>(W2);

    // CSR build (independent of GEMMs; interleave for overlap)
    zero_deg_kernel<<<(M + 255) / 256, 256>>>(M);
    hist_kernel<<<(E + 255) / 256, 256>>>(row, E);
    scan_kernel<<<1, 1024>>>(M);
    scatter_kernel<<<(E + 255) / 256, 256>>>(row, col, ew, E);

    // dense front-end on tensor cores
    dim3 g1((M + 127) / 128, HID_DIM / 256);
    gemm1_mma_kernel<<<g1, 512, G1_SMEM>>>(b1, M);
    gemm2_mma_kernel<<<(M + 127) / 128, 256, G2_SMEM>>>(b2, M);

    // 10 propagation hops (fp16 features)
    int spmm_blocks = (M * 32 + 255) / 256;
    for (int hop = 1; hop <= HOPS; ++hop)
        spmm_kernel<<<spmm_blocks, 256>>>(hop, M);

    // gated combine
    combine_kernel<<<spmm_blocks, 256>>>(s, (float*)d_out, M);
}

// round 5
// speedup vs baseline: 2.1078x; 1.3926x over previous
#include <cuda_runtime.h>
#include <cuda_fp16.h>
#include <math.h>
#include <stdint.h>

#define N_NODES 100000
#define E_MAX   3300000
#define IN_DIM  512
#define HID_DIM 512
#define OUT_DIM 64
#define HOPS    10

// ---------------- scratch (static device globals; no allocations) ----------------
__device__ __half g_xh[(size_t)N_NODES * IN_DIM];                 // 102.4 MB
__device__ __half g_h1h[(size_t)N_NODES * HID_DIM];               // 102.4 MB
__device__ __half g_Hh[(size_t)(HOPS + 1) * N_NODES * OUT_DIM];   // 140.8 MB
__device__ __half g_w1t[(size_t)HID_DIM * IN_DIM];                // 0.5 MB ([n][k])
__device__ __half g_w2t[(size_t)OUT_DIM * HID_DIM];               // 64 KB ([n][k])
__device__ int   g_deg[N_NODES];
__device__ int   g_rowptr[N_NODES + 1];
__device__ int   g_cursor[N_NODES];
__device__ int2  g_edge[E_MAX];                                   // (col, w bits)

// ================= PTX helpers =================
__device__ __forceinline__ uint32_t smem_u32(const void* p) {
    uint32_t a;
    asm("{ .reg .u64 t; cvta.to.shared.u64 t, %1; cvt.u32.u64 %0, t; }" : "=r"(a) : "l"(p));
    return a;
}
__device__ __forceinline__ void cp_async16(uint32_t s, const void* g, int sz) {
    asm volatile("cp.async.cg.shared.global [%0], [%1], 16, %2;"
                 :: "r"(s), "l"(g), "r"(sz) : "memory");
}
__device__ __forceinline__ void cp_commit() {
    asm volatile("cp.async.commit_group;" ::: "memory");
}
template <int N>
__device__ __forceinline__ void cp_wait() {
    asm volatile("cp.async.wait_group %0;" :: "n"(N) : "memory");
}
__device__ __forceinline__ void ldsm_x4(uint32_t* r, uint32_t addr) {
    asm volatile("ldmatrix.sync.aligned.m8n8.x4.shared.b16 {%0,%1,%2,%3}, [%4];"
                 : "=r"(r[0]), "=r"(r[1]), "=r"(r[2]), "=r"(r[3]) : "r"(addr));
}
__device__ __forceinline__ void mma_f16(float* d, const uint32_t* a, const uint32_t* b) {
    asm volatile(
        "mma.sync.aligned.m16n8k16.row.col.f32.f16.f16.f32 "
        "{%0,%1,%2,%3}, {%4,%5,%6,%7}, {%8,%9}, {%0,%1,%2,%3};"
        : "+f"(d[0]), "+f"(d[1]), "+f"(d[2]), "+f"(d[3])
        : "r"(a[0]), "r"(a[1]), "r"(a[2]), "r"(a[3]), "r"(b[0]), "r"(b[1]));
}

// ---------------- fp16 conversion kernels ----------------
__global__ void conv_x_kernel(const float* __restrict__ x, size_t n4)
{
    size_t i = (size_t)blockIdx.x * blockDim.x + threadIdx.x;
    if (i >= n4) return;
    float4 v = *(const float4*)(x + i * 4);
    union { __half2 h[2]; uint2 u; } o;
    o.h[0] = __floats2half2_rn(v.x, v.y);
    o.h[1] = __floats2half2_rn(v.z, v.w);
    *(uint2*)(g_xh + i * 4) = o.u;
}

__global__ void conv_w1_kernel(const float* __restrict__ W1)
{
    int i = blockIdx.x * blockDim.x + threadIdx.x;  // i = n*512 + k
    if (i >= HID_DIM * IN_DIM) return;
    int n = i >> 9, k = i & 511;
    g_w1t[i] = __float2half_rn(W1[k * HID_DIM + n]);
}

__global__ void conv_w2_kernel(const float* __restrict__ W2)
{
    int i = blockIdx.x * blockDim.x + threadIdx.x;  // i = n*512 + k
    if (i >= OUT_DIM * HID_DIM) return;
    int n = i >> 9, k = i & 511;
    g_w2t[i] = __float2half_rn(W2[k * OUT_DIM + n]);
}

// ============ GEMM1 (mma.sync fp16): h1 = relu(x @ W1 + b1) -> fp16 ============
// CTA 128x256, 16 warps (4M x 4N), warp tile 32x64. K chunks of 64, 3-stage.
#define G1_NKC   (IN_DIM / 64)        // 8
#define G1_P     144
#define G1_AT    (128 * G1_P)         // 18432
#define G1_BT    (256 * G1_P)         // 36864
#define G1_ST    (G1_AT + G1_BT)      // 55296
#define G1_SMEM  (3 * G1_ST)          // 165888

__global__ __launch_bounds__(512, 1) void gemm1_mma_kernel(const float* __restrict__ bias, int M)
{
    extern __shared__ char smem[];
    const int tid  = threadIdx.x;
    const int wid  = tid >> 5, lane = tid & 31;
    const int wm   = wid & 3,  wn   = wid >> 2;      // 4 x 4 warps
    const int brow = blockIdx.x * 128, bcol = blockIdx.y * 256;

    const uint32_t sbase = smem_u32(smem);
    const uint32_t AOFF = 0, BOFF = G1_AT;

    float d[2][8][4];
#pragma unroll
    for (int i = 0; i < 2; i++)
#pragma unroll
        for (int j = 0; j < 8; j++)
#pragma unroll
            for (int k = 0; k < 4; k++) d[i][j][k] = 0.f;

    auto issue_load = [&](int kc, int st) {
        const int k0 = kc * 64;
        const uint32_t s0 = sbase + st * G1_ST;
#pragma unroll
        for (int i = 0; i < 2; i++) {  // A: 1024 segs of 16B
            int seg = tid + i * 512;
            int row = seg >> 3, sc = seg & 7;
            uint32_t soff = row * G1_P + sc * 16;
            int ar = brow + row;
            int ok = (ar < M);
            size_t gA = (size_t)(ok ? ar : 0) * IN_DIM + k0 + sc * 8;
            cp_async16(s0 + AOFF + soff, g_xh + gA, ok ? 16 : 0);
        }
#pragma unroll
        for (int i = 0; i < 4; i++) {  // B: 2048 segs
            int seg = tid + i * 512;
            int row = seg >> 3, sc = seg & 7;
            uint32_t soff = row * G1_P + sc * 16;
            size_t gB = (size_t)(bcol + row) * IN_DIM + k0 + sc * 8;
            cp_async16(s0 + BOFF + soff, g_w1t + gB, 16);
        }
        cp_commit();
    };

    issue_load(0, 0);
    issue_load(1, 1);

    for (int kc = 0; kc < G1_NKC; kc++) {
        if (kc == G1_NKC - 1) cp_wait<0>(); else cp_wait<1>();
        __syncthreads();
        if (kc + 2 < G1_NKC) issue_load(kc + 2, (kc + 2) % 3);

        const uint32_t s0 = sbase + (kc % 3) * G1_ST;
#pragma unroll
        for (int ks = 0; ks < 4; ks++) {
            uint32_t a[2][4];
            const int ac = (ks * 16 + (lane >> 4) * 8) * 2;
#pragma unroll
            for (int mt = 0; mt < 2; mt++) {
                int r = wm * 32 + mt * 16 + (lane & 15);
                ldsm_x4(a[mt], s0 + AOFF + r * G1_P + ac);
            }
            const int bn_l = (lane >> 4) * 8 + (lane & 7);
            const int bk   = (ks * 16 + ((lane >> 3) & 1) * 8) * 2;
#pragma unroll
            for (int p = 0; p < 4; p++) {
                uint32_t b[4];
                int n = wn * 64 + p * 16 + bn_l;
                ldsm_x4(b, s0 + BOFF + n * G1_P + bk);
#pragma unroll
                for (int mt = 0; mt < 2; mt++) {
#pragma unroll
                    for (int j = 0; j < 2; j++)
                        mma_f16(d[mt][2 * p + j], a[mt], b + 2 * j);
                }
            }
        }
    }

    // ---- epilogue: relu(acc + bias) -> fp16 h1
#pragma unroll
    for (int mt = 0; mt < 2; mt++) {
        int row0 = brow + wm * 32 + mt * 16 + (lane >> 2);
#pragma unroll
        for (int nt = 0; nt < 8; nt++) {
            int col = bcol + wn * 64 + nt * 8 + (lane & 3) * 2;
            float b0 = bias[col], b1 = bias[col + 1];
#pragma unroll
            for (int h = 0; h < 2; h++) {
                int r = row0 + h * 8;
                if (r >= M) continue;
                __half2 hv = __floats2half2_rn(fmaxf(d[mt][nt][2 * h + 0] + b0, 0.f),
                                               fmaxf(d[mt][nt][2 * h + 1] + b1, 0.f));
                *(__half2*)(g_h1h + (size_t)r * HID_DIM + col) = hv;
            }
        }
    }
}

// ============ GEMM2 (mma.sync fp16): H0 = h1 @ W2 + b2 -> fp16 ============
// CTA 128x64, 8 warps (4M x 2N), warp tile 32x32. K chunks of 64, 3-stage.
#define G2_NKC   (HID_DIM / 64)       // 8
#define G2_P     144
#define G2_AT    (128 * G2_P)         // 18432
#define G2_BT    (64 * G2_P)          // 9216
#define G2_ST    (G2_AT + G2_BT)      // 27648
#define G2_SMEM  (3 * G2_ST)          // 82944

__global__ __launch_bounds__(256, 1) void gemm2_mma_kernel(const float* __restrict__ bias, int M)
{
    extern __shared__ char smem[];
    const int tid  = threadIdx.x;
    const int wid  = tid >> 5, lane = tid & 31;
    const int wm   = wid & 3,  wn   = wid >> 2;      // 4 x 2 warps
    const int brow = blockIdx.x * 128;

    const uint32_t sbase = smem_u32(smem);
    const uint32_t AOFF = 0, BOFF = G2_AT;

    float d[2][4][4];
#pragma unroll
    for (int i = 0; i < 2; i++)
#pragma unroll
        for (int j = 0; j < 4; j++)
#pragma unroll
            for (int k = 0; k < 4; k++) d[i][j][k] = 0.f;

    auto issue_load = [&](int kc, int st) {
        const int k0 = kc * 64;
        const uint32_t s0 = sbase + st * G2_ST;
#pragma unroll
        for (int i = 0; i < 4; i++) {  // A: 1024 segs
            int seg = tid + i * 256;
            int row = seg >> 3, sc = seg & 7;
            uint32_t soff = row * G2_P + sc * 16;
            int ar = brow + row;
            int ok = (ar < M);
            size_t gA = (size_t)(ok ? ar : 0) * HID_DIM + k0 + sc * 8;
            cp_async16(s0 + AOFF + soff, g_h1h + gA, ok ? 16 : 0);
        }
#pragma unroll
        for (int i = 0; i < 2; i++) {  // B: 512 segs
            int seg = tid + i * 256;
            int row = seg >> 3, sc = seg & 7;
            uint32_t soff = row * G2_P + sc * 16;
            size_t gB = (size_t)row * HID_DIM + k0 + sc * 8;
            cp_async16(s0 + BOFF + soff, g_w2t + gB, 16);
        }
        cp_commit();
    };

    issue_load(0, 0);
    issue_load(1, 1);

    for (int kc = 0; kc < G2_NKC; kc++) {
        if (kc == G2_NKC - 1) cp_wait<0>(); else cp_wait<1>();
        __syncthreads();
        if (kc + 2 < G2_NKC) issue_load(kc + 2, (kc + 2) % 3);

        const uint32_t s0 = sbase + (kc % 3) * G2_ST;
#pragma unroll
        for (int ks = 0; ks < 4; ks++) {
            uint32_t a[2][4];
            const int ac = (ks * 16 + (lane >> 4) * 8) * 2;
#pragma unroll
            for (int mt = 0; mt < 2; mt++) {
                int r = wm * 32 + mt * 16 + (lane & 15);
                ldsm_x4(a[mt], s0 + AOFF + r * G2_P + ac);
            }
            const int bn_l = (lane >> 4) * 8 + (lane & 7);
            const int bk   = (ks * 16 + ((lane >> 3) & 1) * 8) * 2;
#pragma unroll
            for (int p = 0; p < 2; p++) {
                uint32_t b[4];
                int n = wn * 32 + p * 16 + bn_l;
                ldsm_x4(b, s0 + BOFF + n * G2_P + bk);
#pragma unroll
                for (int mt = 0; mt < 2; mt++) {
#pragma unroll
                    for (int j = 0; j < 2; j++)
                        mma_f16(d[mt][2 * p + j], a[mt], b + 2 * j);
                }
            }
        }
    }

    // ---- epilogue: + bias, write fp16 H0
#pragma unroll
    for (int mt = 0; mt < 2; mt++) {
        int row0 = brow + wm * 32 + mt * 16 + (lane >> 2);
#pragma unroll
        for (int nt = 0; nt < 4; nt++) {
            int col = wn * 32 + nt * 8 + (lane & 3) * 2;
            float b0 = bias[col], b1 = bias[col + 1];
#pragma unroll
            for (int h = 0; h < 2; h++) {
                int r = row0 + h * 8;
                if (r >= M) continue;
                __half2 hv = __floats2half2_rn(d[mt][nt][2 * h + 0] + b0,
                                               d[mt][nt][2 * h + 1] + b1);
                *(__half2*)(g_Hh + (size_t)r * OUT_DIM + col) = hv;
            }
        }
    }
}

// ---------------- CSR build ----------------
__global__ void zero_deg_kernel(int n)
{
    int i = blockIdx.x * blockDim.x + threadIdx.x;
    if (i < n) g_deg[i] = 0;
}

__global__ void hist_kernel(const int* __restrict__ row, int E)
{
    int e = blockIdx.x * blockDim.x + threadIdx.x;
    if (e < E) atomicAdd(&g_deg[row[e]], 1);
}

__global__ __launch_bounds__(1024) void scan_kernel(int n)
{
    __shared__ int sums[1024];
    int tid = threadIdx.x;
    int per = (n + 1023) >> 10;
    int start = tid * per;
    int end = min(start + per, n);

    int s = 0;
    for (int i = start; i < end; ++i) s += g_deg[i];
    sums[tid] = s;
    __syncthreads();

    for (int off = 1; off < 1024; off <<= 1) {
        int v = 0;
        if (tid >= off) v = sums[tid - off];
        __syncthreads();
        sums[tid] += v;
        __syncthreads();
    }

    int run = sums[tid] - s;
    for (int i = start; i < end; ++i) {
        g_rowptr[i] = run;
        g_cursor[i] = run;
        run += g_deg[i];
    }
    if (tid == 1023) g_rowptr[n] = sums[1023];
}

__global__ void scatter_kernel(const int* __restrict__ row, const int* __restrict__ col,
                               const float* __restrict__ w, int E)
{
    int e = blockIdx.x * blockDim.x + threadIdx.x;
    if (e >= E) return;
    int r = row[e];
    int pos = atomicAdd(&g_cursor[r], 1);
    g_edge[pos] = make_int2(col[e], __float_as_int(w[e]));
}

// ---------------- SpMM hop (fp16 features, 4-edge unroll) ----------------
__global__ __launch_bounds__(256) void spmm_kernel(int hop, int n)
{
    int warp = (blockIdx.x * blockDim.x + threadIdx.x) >> 5;
    int lane = threadIdx.x & 31;
    if (warp >= n) return;

    const __half2* __restrict__ hin =
        (const __half2*)(g_Hh + (size_t)(hop - 1) * N_NODES * OUT_DIM);
    __half2* __restrict__ hout =
        (__half2*)(g_Hh + (size_t)hop * N_NODES * OUT_DIM);

    int s  = g_rowptr[warp];
    int e2 = g_rowptr[warp + 1];

    float ax = 0.f, ay = 0.f;
    int i = s;
    for (; i + 3 < e2; i += 4) {
        int2 e0 = g_edge[i],     e1 = g_edge[i + 1];
        int2 e2b = g_edge[i + 2], e3 = g_edge[i + 3];
        float2 v0 = __half22float2(hin[(size_t)e0.x  * 32 + lane]);
        float2 v1 = __half22float2(hin[(size_t)e1.x  * 32 + lane]);
        float2 v2 = __half22float2(hin[(size_t)e2b.x * 32 + lane]);
        float2 v3 = __half22float2(hin[(size_t)e3.x  * 32 + lane]);
        float w0 = __int_as_float(e0.y),  w1 = __int_as_float(e1.y);
        float w2 = __int_as_float(e2b.y), w3 = __int_as_float(e3.y);
        ax += w0 * v0.x + w1 * v1.x + w2 * v2.x + w3 * v3.x;
        ay += w0 * v0.y + w1 * v1.y + w2 * v2.y + w3 * v3.y;
    }
    for (; i < e2; ++i) {
        int2 e0 = g_edge[i];
        float w0 = __int_as_float(e0.y);
        float2 v0 = __half22float2(hin[(size_t)e0.x * 32 + lane]);
        ax += w0 * v0.x; ay += w0 * v0.y;
    }
    hout[(size_t)warp * 32 + lane] = __floats2half2_rn(ax, ay);
}

// ---------------- Combine ----------------
__global__ __launch_bounds__(256) void combine_kernel(
    const float* __restrict__ s, float* __restrict__ out, int n)
{
    int warp = (blockIdx.x * blockDim.x + threadIdx.x) >> 5;
    int lane = threadIdx.x & 31;
    if (warp >= n) return;

    float s0 = s[lane * 2 + 0];
    float s1 = s[lane * 2 + 1];

    float ox = 0.f, oy = 0.f;
#pragma unroll
    for (int k = 0; k <= HOPS; k++) {
        const __half2* hk = (const __half2*)(g_Hh + (size_t)k * N_NODES * OUT_DIM);
        float2 h = __half22float2(hk[(size_t)warp * 32 + lane]);
        float d = h.x * s0 + h.y * s1;
#pragma unroll
        for (int off = 16; off; off >>= 1) d += __shfl_xor_sync(0xffffffffu, d, off);
        float sg = 1.f / (1.f + expf(-d));
        ox += sg * h.x;
        oy += sg * h.y;
    }
    ((float2*)out)[(size_t)warp * 32 + lane] = make_float2(ox, oy);
}

// ---------------- launch ----------------
extern "C" void kernel_launch(void* const* d_in, const int* in_sizes, int n_in,
                              void* d_out, int out_size)
{
    const float* x   = (const float*)d_in[0];
    const int*   row = (const int*)  d_in[1];
    const int*   col = (const int*)  d_in[2];
    const float* ew  = (const float*)d_in[3];
    const float* W1  = (const float*)d_in[4];
    const float* b1  = (const float*)d_in[5];
    const float* W2  = (const float*)d_in[6];
    const float* b2  = (const float*)d_in[7];
    const float* s   = (const float*)d_in[8];

    int M = in_sizes[0] / IN_DIM;  // 100000
    int E = in_sizes[1];           // 3300000

    static bool attr_set = false;
    if (!attr_set) {
        cudaFuncSetAttribute(gemm1_mma_kernel,
                             cudaFuncAttributeMaxDynamicSharedMemorySize, G1_SMEM);
        cudaFuncSetAttribute(gemm2_mma_kernel,
                             cudaFuncAttributeMaxDynamicSharedMemorySize, G2_SMEM);
        attr_set = true;
    }

    // fp16 conversions (launches 0-2)
    size_t n4 = (size_t)M * IN_DIM / 4;
    conv_x_kernel<<<(unsigned)((n4 + 255) / 256), 256>>>(x, n4);
    conv_w1_kernel<<<(HID_DIM * IN_DIM + 255) / 256, 256>>>(W1);
    conv_w2_kernel<<<(OUT_DIM * HID_DIM + 255) / 256, 256>>>(W2);

    // dense front-end on tensor cores (gemm1 = launch index 3 for profiling)
    dim3 g1((M + 127) / 128, HID_DIM / 256);
    gemm1_mma_kernel<<<g1, 512, G1_SMEM>>>(b1, M);
    gemm2_mma_kernel<<<(M + 127) / 128, 256, G2_SMEM>>>(b2, M);

    // CSR build
    zero_deg_kernel<<<(M + 255) / 256, 256>>>(M);
    hist_kernel<<<(E + 255) / 256, 256>>>(row, E);
    scan_kernel<<<1, 1024>>>(M);
    scatter_kernel<<<(E + 255) / 256, 256>>>(row, col, ew, E);

    // 10 propagation hops (fp16 features)
    int spmm_blocks = (M * 32 + 255) / 256;
    for (int hop = 1; hop <= HOPS; ++hop)
        spmm_kernel<<<spmm_blocks, 256>>>(hop, M);

    // gated combine
    combine_kernel<<<spmm_blocks, 256>>>(s, (float*)d_out, M);
}

// round 6
// speedup vs baseline: 2.1232x; 1.0073x over previous
#include <cuda_runtime.h>
#include <cuda_fp16.h>
#include <math.h>
#include <stdint.h>

#define N_NODES 100000
#define E_MAX   3300000
#define IN_DIM  512
#define HID_DIM 512
#define OUT_DIM 64
#define HOPS    10

// ---------------- scratch (static device globals; no allocations) ----------------
__device__ __half g_xh[(size_t)N_NODES * IN_DIM];                 // 102.4 MB
__device__ __half g_h1h[(size_t)N_NODES * HID_DIM];               // 102.4 MB
__device__ __half g_Hh[(size_t)(HOPS + 1) * N_NODES * OUT_DIM];   // 140.8 MB
__device__ __half g_w1t[(size_t)HID_DIM * IN_DIM];                // 0.5 MB ([n][k])
__device__ __half g_w2t[(size_t)OUT_DIM * HID_DIM];               // 64 KB ([n][k])
__device__ int   g_deg[N_NODES];
__device__ int   g_rowptr[N_NODES + 1];
__device__ int   g_cursor[N_NODES];
__device__ int2  g_edge[E_MAX];                                   // (col, half2(w,w) bits)

// ================= PTX helpers =================
__device__ __forceinline__ uint32_t smem_u32(const void* p) {
    uint32_t a;
    asm("{ .reg .u64 t; cvta.to.shared.u64 t, %1; cvt.u32.u64 %0, t; }" : "=r"(a) : "l"(p));
    return a;
}
__device__ __forceinline__ void cp_async16(uint32_t s, const void* g, int sz) {
    asm volatile("cp.async.cg.shared.global [%0], [%1], 16, %2;"
                 :: "r"(s), "l"(g), "r"(sz) : "memory");
}
__device__ __forceinline__ void cp_commit() {
    asm volatile("cp.async.commit_group;" ::: "memory");
}
template <int N>
__device__ __forceinline__ void cp_wait() {
    asm volatile("cp.async.wait_group %0;" :: "n"(N) : "memory");
}
__device__ __forceinline__ void ldsm_x4(uint32_t* r, uint32_t addr) {
    asm volatile("ldmatrix.sync.aligned.m8n8.x4.shared.b16 {%0,%1,%2,%3}, [%4];"
                 : "=r"(r[0]), "=r"(r[1]), "=r"(r[2]), "=r"(r[3]) : "r"(addr));
}
__device__ __forceinline__ void mma_f16(float* d, const uint32_t* a, const uint32_t* b) {
    asm volatile(
        "mma.sync.aligned.m16n8k16.row.col.f32.f16.f16.f32 "
        "{%0,%1,%2,%3}, {%4,%5,%6,%7}, {%8,%9}, {%0,%1,%2,%3};"
        : "+f"(d[0]), "+f"(d[1]), "+f"(d[2]), "+f"(d[3])
        : "r"(a[0]), "r"(a[1]), "r"(a[2]), "r"(a[3]), "r"(b[0]), "r"(b[1]));
}
__device__ __forceinline__ __half2 bits2h2(int b) {
    union { int i; __half2 h; } u; u.i = b; return u.h;
}
__device__ __forceinline__ int h22bits(__half2 h) {
    union { int i; __half2 h; } u; u.h = h; return u.i;
}

// ---------------- fp16 conversion kernels ----------------
__global__ void conv_x_kernel(const float* __restrict__ x, size_t n4)
{
    size_t i = (size_t)blockIdx.x * blockDim.x + threadIdx.x;
    if (i >= n4) return;
    float4 v = *(const float4*)(x + i * 4);
    union { __half2 h[2]; uint2 u; } o;
    o.h[0] = __floats2half2_rn(v.x, v.y);
    o.h[1] = __floats2half2_rn(v.z, v.w);
    *(uint2*)(g_xh + i * 4) = o.u;
}

__global__ void conv_w1_kernel(const float* __restrict__ W1)
{
    int i = blockIdx.x * blockDim.x + threadIdx.x;  // i = n*512 + k
    if (i >= HID_DIM * IN_DIM) return;
    int n = i >> 9, k = i & 511;
    g_w1t[i] = __float2half_rn(W1[k * HID_DIM + n]);
}

__global__ void conv_w2_kernel(const float* __restrict__ W2)
{
    int i = blockIdx.x * blockDim.x + threadIdx.x;  // i = n*512 + k
    if (i >= OUT_DIM * HID_DIM) return;
    int n = i >> 9, k = i & 511;
    g_w2t[i] = __float2half_rn(W2[k * OUT_DIM + n]);
}

// ============ GEMM1 (mma.sync fp16): h1 = relu(x @ W1 + b1) -> fp16 ============
// CTA 128x256, 16 warps (4M x 4N), warp tile 32x64. K chunks of 64, 3-stage.
#define G1_NKC   (IN_DIM / 64)        // 8
#define G1_P     144
#define G1_AT    (128 * G1_P)         // 18432
#define G1_BT    (256 * G1_P)         // 36864
#define G1_ST    (G1_AT + G1_BT)      // 55296
#define G1_SMEM  (3 * G1_ST)          // 165888

__global__ __launch_bounds__(512, 1) void gemm1_mma_kernel(const float* __restrict__ bias, int M)
{
    extern __shared__ char smem[];
    const int tid  = threadIdx.x;
    const int wid  = tid >> 5, lane = tid & 31;
    const int wm   = wid & 3,  wn   = wid >> 2;      // 4 x 4 warps
    const int brow = blockIdx.x * 128, bcol = blockIdx.y * 256;

    const uint32_t sbase = smem_u32(smem);
    const uint32_t AOFF = 0, BOFF = G1_AT;

    float d[2][8][4];
#pragma unroll
    for (int i = 0; i < 2; i++)
#pragma unroll
        for (int j = 0; j < 8; j++)
#pragma unroll
            for (int k = 0; k < 4; k++) d[i][j][k] = 0.f;

    auto issue_load = [&](int kc, int st) {
        const int k0 = kc * 64;
        const uint32_t s0 = sbase + st * G1_ST;
#pragma unroll
        for (int i = 0; i < 2; i++) {  // A: 1024 segs of 16B
            int seg = tid + i * 512;
            int row = seg >> 3, sc = seg & 7;
            uint32_t soff = row * G1_P + sc * 16;
            int ar = brow + row;
            int ok = (ar < M);
            size_t gA = (size_t)(ok ? ar : 0) * IN_DIM + k0 + sc * 8;
            cp_async16(s0 + AOFF + soff, g_xh + gA, ok ? 16 : 0);
        }
#pragma unroll
        for (int i = 0; i < 4; i++) {  // B: 2048 segs
            int seg = tid + i * 512;
            int row = seg >> 3, sc = seg & 7;
            uint32_t soff = row * G1_P + sc * 16;
            size_t gB = (size_t)(bcol + row) * IN_DIM + k0 + sc * 8;
            cp_async16(s0 + BOFF + soff, g_w1t + gB, 16);
        }
        cp_commit();
    };

    issue_load(0, 0);
    issue_load(1, 1);

    for (int kc = 0; kc < G1_NKC; kc++) {
        if (kc == G1_NKC - 1) cp_wait<0>(); else cp_wait<1>();
        __syncthreads();
        if (kc + 2 < G1_NKC) issue_load(kc + 2, (kc + 2) % 3);

        const uint32_t s0 = sbase + (kc % 3) * G1_ST;
#pragma unroll
        for (int ks = 0; ks < 4; ks++) {
            uint32_t a[2][4];
            const int ac = (ks * 16 + (lane >> 4) * 8) * 2;
#pragma unroll
            for (int mt = 0; mt < 2; mt++) {
                int r = wm * 32 + mt * 16 + (lane & 15);
                ldsm_x4(a[mt], s0 + AOFF + r * G1_P + ac);
            }
            const int bn_l = (lane >> 4) * 8 + (lane & 7);
            const int bk   = (ks * 16 + ((lane >> 3) & 1) * 8) * 2;
#pragma unroll
            for (int p = 0; p < 4; p++) {
                uint32_t b[4];
                int n = wn * 64 + p * 16 + bn_l;
                ldsm_x4(b, s0 + BOFF + n * G1_P + bk);
#pragma unroll
                for (int mt = 0; mt < 2; mt++) {
#pragma unroll
                    for (int j = 0; j < 2; j++)
                        mma_f16(d[mt][2 * p + j], a[mt], b + 2 * j);
                }
            }
        }
    }

    // ---- epilogue: relu(acc + bias) -> fp16 h1
#pragma unroll
    for (int mt = 0; mt < 2; mt++) {
        int row0 = brow + wm * 32 + mt * 16 + (lane >> 2);
#pragma unroll
        for (int nt = 0; nt < 8; nt++) {
            int col = bcol + wn * 64 + nt * 8 + (lane & 3) * 2;
            float b0 = bias[col], b1 = bias[col + 1];
#pragma unroll
            for (int h = 0; h < 2; h++) {
                int r = row0 + h * 8;
                if (r >= M) continue;
                __half2 hv = __floats2half2_rn(fmaxf(d[mt][nt][2 * h + 0] + b0, 0.f),
                                               fmaxf(d[mt][nt][2 * h + 1] + b1, 0.f));
                *(__half2*)(g_h1h + (size_t)r * HID_DIM + col) = hv;
            }
        }
    }
}

// ============ GEMM2 (mma.sync fp16): H0 = h1 @ W2 + b2 -> fp16 ============
#define G2_NKC   (HID_DIM / 64)       // 8
#define G2_P     144
#define G2_AT    (128 * G2_P)         // 18432
#define G2_BT    (64 * G2_P)          // 9216
#define G2_ST    (G2_AT + G2_BT)      // 27648
#define G2_SMEM  (3 * G2_ST)          // 82944

__global__ __launch_bounds__(256, 1) void gemm2_mma_kernel(const float* __restrict__ bias, int M)
{
    extern __shared__ char smem[];
    const int tid  = threadIdx.x;
    const int wid  = tid >> 5, lane = tid & 31;
    const int wm   = wid & 3,  wn   = wid >> 2;      // 4 x 2 warps
    const int brow = blockIdx.x * 128;

    const uint32_t sbase = smem_u32(smem);
    const uint32_t AOFF = 0, BOFF = G2_AT;

    float d[2][4][4];
#pragma unroll
    for (int i = 0; i < 2; i++)
#pragma unroll
        for (int j = 0; j < 4; j++)
#pragma unroll
            for (int k = 0; k < 4; k++) d[i][j][k] = 0.f;

    auto issue_load = [&](int kc, int st) {
        const int k0 = kc * 64;
        const uint32_t s0 = sbase + st * G2_ST;
#pragma unroll
        for (int i = 0; i < 4; i++) {  // A: 1024 segs
            int seg = tid + i * 256;
            int row = seg >> 3, sc = seg & 7;
            uint32_t soff = row * G2_P + sc * 16;
            int ar = brow + row;
            int ok = (ar < M);
            size_t gA = (size_t)(ok ? ar : 0) * HID_DIM + k0 + sc * 8;
            cp_async16(s0 + AOFF + soff, g_h1h + gA, ok ? 16 : 0);
        }
#pragma unroll
        for (int i = 0; i < 2; i++) {  // B: 512 segs
            int seg = tid + i * 256;
            int row = seg >> 3, sc = seg & 7;
            uint32_t soff = row * G2_P + sc * 16;
            size_t gB = (size_t)row * HID_DIM + k0 + sc * 8;
            cp_async16(s0 + BOFF + soff, g_w2t + gB, 16);
        }
        cp_commit();
    };

    issue_load(0, 0);
    issue_load(1, 1);

    for (int kc = 0; kc < G2_NKC; kc++) {
        if (kc == G2_NKC - 1) cp_wait<0>(); else cp_wait<1>();
        __syncthreads();
        if (kc + 2 < G2_NKC) issue_load(kc + 2, (kc + 2) % 3);

        const uint32_t s0 = sbase + (kc % 3) * G2_ST;
#pragma unroll
        for (int ks = 0; ks < 4; ks++) {
            uint32_t a[2][4];
            const int ac = (ks * 16 + (lane >> 4) * 8) * 2;
#pragma unroll
            for (int mt = 0; mt < 2; mt++) {
                int r = wm * 32 + mt * 16 + (lane & 15);
                ldsm_x4(a[mt], s0 + AOFF + r * G2_P + ac);
            }
            const int bn_l = (lane >> 4) * 8 + (lane & 7);
            const int bk   = (ks * 16 + ((lane >> 3) & 1) * 8) * 2;
#pragma unroll
            for (int p = 0; p < 2; p++) {
                uint32_t b[4];
                int n = wn * 32 + p * 16 + bn_l;
                ldsm_x4(b, s0 + BOFF + n * G2_P + bk);
#pragma unroll
                for (int mt = 0; mt < 2; mt++) {
#pragma unroll
                    for (int j = 0; j < 2; j++)
                        mma_f16(d[mt][2 * p + j], a[mt], b + 2 * j);
                }
            }
        }
    }

    // ---- epilogue: + bias, write fp16 H0
#pragma unroll
    for (int mt = 0; mt < 2; mt++) {
        int row0 = brow + wm * 32 + mt * 16 + (lane >> 2);
#pragma unroll
        for (int nt = 0; nt < 4; nt++) {
            int col = wn * 32 + nt * 8 + (lane & 3) * 2;
            float b0 = bias[col], b1 = bias[col + 1];
#pragma unroll
            for (int h = 0; h < 2; h++) {
                int r = row0 + h * 8;
                if (r >= M) continue;
                __half2 hv = __floats2half2_rn(d[mt][nt][2 * h + 0] + b0,
                                               d[mt][nt][2 * h + 1] + b1);
                *(__half2*)(g_Hh + (size_t)r * OUT_DIM + col) = hv;
            }
        }
    }
}

// ---------------- CSR build ----------------
__global__ void zero_deg_kernel(int n)
{
    int i = blockIdx.x * blockDim.x + threadIdx.x;
    if (i < n) g_deg[i] = 0;
}

__global__ void hist_kernel(const int* __restrict__ row, int E)
{
    int e = blockIdx.x * blockDim.x + threadIdx.x;
    if (e < E) atomicAdd(&g_deg[row[e]], 1);
}

__global__ __launch_bounds__(1024) void scan_kernel(int n)
{
    __shared__ int sums[1024];
    int tid = threadIdx.x;
    int per = (n + 1023) >> 10;
    int start = tid * per;
    int end = min(start + per, n);

    int s = 0;
    for (int i = start; i < end; ++i) s += g_deg[i];
    sums[tid] = s;
    __syncthreads();

    for (int off = 1; off < 1024; off <<= 1) {
        int v = 0;
        if (tid >= off) v = sums[tid - off];
        __syncthreads();
        sums[tid] += v;
        __syncthreads();
    }

    int run = sums[tid] - s;
    for (int i = start; i < end; ++i) {
        g_rowptr[i] = run;
        g_cursor[i] = run;
        run += g_deg[i];
    }
    if (tid == 1023) g_rowptr[n] = sums[1023];
}

__global__ void scatter_kernel(const int* __restrict__ row, const int* __restrict__ col,
                               const float* __restrict__ w, int E)
{
    int e = blockIdx.x * blockDim.x + threadIdx.x;
    if (e >= E) return;
    int r = row[e];
    int pos = atomicAdd(&g_cursor[r], 1);
    __half hw = __float2half_rn(w[e]);
    __half2 w2 = __half2half2(hw);
    g_edge[pos] = make_int2(col[e], h22bits(w2));
}

// ---------------- SpMM hop: smem-staged edges + HFMA2 accumulation ----------------
// warp per row; 32-edge smem batches; fp16 accum in 2 regs, flushed to fp32 every 8.
__global__ __launch_bounds__(256) void spmm_kernel(int hop, int n)
{
    __shared__ int2 ebuf[8][32];
    const int wslot = threadIdx.x >> 5;
    const int warp = (blockIdx.x * blockDim.x + threadIdx.x) >> 5;
    const int lane = threadIdx.x & 31;
    if (warp >= n) return;

    const __half2* __restrict__ hin =
        (const __half2*)(g_Hh + (size_t)(hop - 1) * N_NODES * OUT_DIM);
    __half2* __restrict__ hout =
        (__half2*)(g_Hh + (size_t)hop * N_NODES * OUT_DIM);

    const int s = g_rowptr[warp];
    const int e = g_rowptr[warp + 1];

    float ax = 0.f, ay = 0.f;

    for (int base = s; base < e; base += 32) {
        const int cnt = min(32, e - base);
        if (lane < cnt) ebuf[wslot][lane] = g_edge[base + lane];
        __syncwarp();

        int j = 0;
        for (; j + 8 <= cnt; j += 8) {
            __half2 h0 = __float2half2_rn(0.f);
            __half2 h1 = __float2half2_rn(0.f);
#pragma unroll
            for (int t = 0; t < 8; t += 2) {
                int2 e0 = ebuf[wslot][j + t];
                int2 e1 = ebuf[wslot][j + t + 1];
                __half2 v0 = hin[(size_t)e0.x * 32 + lane];
                __half2 v1 = hin[(size_t)e1.x * 32 + lane];
                h0 = __hfma2(bits2h2(e0.y), v0, h0);
                h1 = __hfma2(bits2h2(e1.y), v1, h1);
            }
            float2 f0 = __half22float2(h0);
            float2 f1 = __half22float2(h1);
            ax += f0.x + f1.x;
            ay += f0.y + f1.y;
        }
        // tail: fp32 path
        for (; j < cnt; ++j) {
            int2 e0 = ebuf[wslot][j];
            float2 v0 = __half22float2(hin[(size_t)e0.x * 32 + lane]);
            float w0 = __half2float(__low2half(bits2h2(e0.y)));
            ax += w0 * v0.x;
            ay += w0 * v0.y;
        }
        __syncwarp();
    }
    hout[(size_t)warp * 32 + lane] = __floats2half2_rn(ax, ay);
}

// ---------------- Combine ----------------
__global__ __launch_bounds__(256) void combine_kernel(
    const float* __restrict__ s, float* __restrict__ out, int n)
{
    int warp = (blockIdx.x * blockDim.x + threadIdx.x) >> 5;
    int lane = threadIdx.x & 31;
    if (warp >= n) return;

    float s0 = s[lane * 2 + 0];
    float s1 = s[lane * 2 + 1];

    float ox = 0.f, oy = 0.f;
#pragma unroll
    for (int k = 0; k <= HOPS; k++) {
        const __half2* hk = (const __half2*)(g_Hh + (size_t)k * N_NODES * OUT_DIM);
        float2 h = __half22float2(hk[(size_t)warp * 32 + lane]);
        float d = h.x * s0 + h.y * s1;
#pragma unroll
        for (int off = 16; off; off >>= 1) d += __shfl_xor_sync(0xffffffffu, d, off);
        float sg = 1.f / (1.f + expf(-d));
        ox += sg * h.x;
        oy += sg * h.y;
    }
    ((float2*)out)[(size_t)warp * 32 + lane] = make_float2(ox, oy);
}

// ---------------- launch ----------------
extern "C" void kernel_launch(void* const* d_in, const int* in_sizes, int n_in,
                              void* d_out, int out_size)
{
    const float* x   = (const float*)d_in[0];
    const int*   row = (const int*)  d_in[1];
    const int*   col = (const int*)  d_in[2];
    const float* ew  = (const float*)d_in[3];
    const float* W1  = (const float*)d_in[4];
    const float* b1  = (const float*)d_in[5];
    const float* W2  = (const float*)d_in[6];
    const float* b2  = (const float*)d_in[7];
    const float* s   = (const float*)d_in[8];

    int M = in_sizes[0] / IN_DIM;  // 100000
    int E = in_sizes[1];           // 3300000

    static bool attr_set = false;
    if (!attr_set) {
        cudaFuncSetAttribute(gemm1_mma_kernel,
                             cudaFuncAttributeMaxDynamicSharedMemorySize, G1_SMEM);
        cudaFuncSetAttribute(gemm2_mma_kernel,
                             cudaFuncAttributeMaxDynamicSharedMemorySize, G2_SMEM);
        attr_set = true;
    }

    // fp16 conversions
    size_t n4 = (size_t)M * IN_DIM / 4;
    conv_x_kernel<<<(unsigned)((n4 + 255) / 256), 256>>>(x, n4);
    conv_w1_kernel<<<(HID_DIM * IN_DIM + 255) / 256, 256>>>(W1);
    conv_w2_kernel<<<(OUT_DIM * HID_DIM + 255) / 256, 256>>>(W2);

    // dense front-end on tensor cores (gemm1 = launch index 3 for profiling)
    dim3 g1((M + 127) / 128, HID_DIM / 256);
    gemm1_mma_kernel<<<g1, 512, G1_SMEM>>>(b1, M);
    gemm2_mma_kernel<<<(M + 127) / 128, 256, G2_SMEM>>>(b2, M);

    // CSR build
    zero_deg_kernel<<<(M + 255) / 256, 256>>>(M);
    hist_kernel<<<(E + 255) / 256, 256>>>(row, E);
    scan_kernel<<<1, 1024>>>(M);
    scatter_kernel<<<(E + 255) / 256, 256>>>(row, col, ew, E);

    // 10 propagation hops (fp16 features)
    int spmm_blocks = (M * 32 + 255) / 256;
    for (int hop = 1; hop <= HOPS; ++hop)
        spmm_kernel<<<spmm_blocks, 256>>>(hop, M);

    // gated combine
    combine_kernel<<<spmm_blocks, 256>>>(s, (float*)d_out, M);
}

// round 7
// speedup vs baseline: 2.4108x; 1.1354x over previous
#include <cuda_runtime.h>
#include <cuda_fp16.h>
#include <math.h>
#include <stdint.h>

#define N_NODES 100000
#define E_MAX   3300000
#define IN_DIM  512
#define HID_DIM 512
#define OUT_DIM 64
#define HOPS    10

// ---------------- scratch (static device globals; no allocations) ----------------
__device__ __half g_xh[(size_t)N_NODES * IN_DIM];                 // 102.4 MB
__device__ __half g_h1h[(size_t)N_NODES * HID_DIM];               // 102.4 MB
__device__ __half g_Hh[(size_t)(HOPS + 1) * N_NODES * OUT_DIM];   // 140.8 MB
__device__ __half g_w1t[(size_t)HID_DIM * IN_DIM];                // 0.5 MB ([n][k])
__device__ __half g_w2t[(size_t)OUT_DIM * HID_DIM];               // 64 KB ([n][k])
__device__ int   g_deg[N_NODES];
__device__ int   g_rowptr[N_NODES + 1];
__device__ int   g_cursor[N_NODES];
__device__ int2  g_edge[E_MAX];                                   // (col, half2(w,w) bits)

// ================= PTX helpers =================
__device__ __forceinline__ uint32_t smem_u32(const void* p) {
    uint32_t a;
    asm("{ .reg .u64 t; cvta.to.shared.u64 t, %1; cvt.u32.u64 %0, t; }" : "=r"(a) : "l"(p));
    return a;
}
__device__ __forceinline__ void cp_async16(uint32_t s, const void* g, int sz) {
    asm volatile("cp.async.cg.shared.global [%0], [%1], 16, %2;"
                 :: "r"(s), "l"(g), "r"(sz) : "memory");
}
__device__ __forceinline__ void cp_commit() {
    asm volatile("cp.async.commit_group;" ::: "memory");
}
template <int N>
__device__ __forceinline__ void cp_wait() {
    asm volatile("cp.async.wait_group %0;" :: "n"(N) : "memory");
}
__device__ __forceinline__ void ldsm_x4(uint32_t* r, uint32_t addr) {
    asm volatile("ldmatrix.sync.aligned.m8n8.x4.shared.b16 {%0,%1,%2,%3}, [%4];"
                 : "=r"(r[0]), "=r"(r[1]), "=r"(r[2]), "=r"(r[3]) : "r"(addr));
}
__device__ __forceinline__ void mma_f16(float* d, const uint32_t* a, const uint32_t* b) {
    asm volatile(
        "mma.sync.aligned.m16n8k16.row.col.f32.f16.f16.f32 "
        "{%0,%1,%2,%3}, {%4,%5,%6,%7}, {%8,%9}, {%0,%1,%2,%3};"
        : "+f"(d[0]), "+f"(d[1]), "+f"(d[2]), "+f"(d[3])
        : "r"(a[0]), "r"(a[1]), "r"(a[2]), "r"(a[3]), "r"(b[0]), "r"(b[1]));
}
__device__ __forceinline__ __half2 bits2h2(int b) {
    union { int i; __half2 h; } u; u.i = b; return u.h;
}
__device__ __forceinline__ int h22bits(__half2 h) {
    union { int i; __half2 h; } u; u.h = h; return u.i;
}

// ---------------- fp16 conversion kernels ----------------
__global__ void conv_x_kernel(const float* __restrict__ x, size_t n4)
{
    size_t i = (size_t)blockIdx.x * blockDim.x + threadIdx.x;
    if (i >= n4) return;
    float4 v = *(const float4*)(x + i * 4);
    union { __half2 h[2]; uint2 u; } o;
    o.h[0] = __floats2half2_rn(v.x, v.y);
    o.h[1] = __floats2half2_rn(v.z, v.w);
    *(uint2*)(g_xh + i * 4) = o.u;
}

__global__ void conv_w1_kernel(const float* __restrict__ W1)
{
    int i = blockIdx.x * blockDim.x + threadIdx.x;  // i = n*512 + k
    if (i >= HID_DIM * IN_DIM) return;
    int n = i >> 9, k = i & 511;
    g_w1t[i] = __float2half_rn(W1[k * HID_DIM + n]);
}

__global__ void conv_w2_kernel(const float* __restrict__ W2)
{
    int i = blockIdx.x * blockDim.x + threadIdx.x;  // i = n*512 + k
    if (i >= OUT_DIM * HID_DIM) return;
    int n = i >> 9, k = i & 511;
    g_w2t[i] = __float2half_rn(W2[k * OUT_DIM + n]);
}

// ============ GEMM1 (mma.sync fp16): h1 = relu(x @ W1 + b1) -> fp16 ============
// CTA 128x256, 16 warps (4M x 4N), warp tile 32x64. K chunks of 64, 3-stage.
#define G1_NKC   (IN_DIM / 64)        // 8
#define G1_P     144
#define G1_AT    (128 * G1_P)         // 18432
#define G1_BT    (256 * G1_P)         // 36864
#define G1_ST    (G1_AT + G1_BT)      // 55296
#define G1_SMEM  (3 * G1_ST)          // 165888

__global__ __launch_bounds__(512, 1) void gemm1_mma_kernel(const float* __restrict__ bias, int M)
{
    extern __shared__ char smem[];
    const int tid  = threadIdx.x;
    const int wid  = tid >> 5, lane = tid & 31;
    const int wm   = wid & 3,  wn   = wid >> 2;      // 4 x 4 warps
    const int brow = blockIdx.x * 128, bcol = blockIdx.y * 256;

    const uint32_t sbase = smem_u32(smem);
    const uint32_t AOFF = 0, BOFF = G1_AT;

    float d[2][8][4];
#pragma unroll
    for (int i = 0; i < 2; i++)
#pragma unroll
        for (int j = 0; j < 8; j++)
#pragma unroll
            for (int k = 0; k < 4; k++) d[i][j][k] = 0.f;

    auto issue_load = [&](int kc, int st) {
        const int k0 = kc * 64;
        const uint32_t s0 = sbase + st * G1_ST;
#pragma unroll
        for (int i = 0; i < 2; i++) {  // A: 1024 segs of 16B
            int seg = tid + i * 512;
            int row = seg >> 3, sc = seg & 7;
            uint32_t soff = row * G1_P + sc * 16;
            int ar = brow + row;
            int ok = (ar < M);
            size_t gA = (size_t)(ok ? ar : 0) * IN_DIM + k0 + sc * 8;
            cp_async16(s0 + AOFF + soff, g_xh + gA, ok ? 16 : 0);
        }
#pragma unroll
        for (int i = 0; i < 4; i++) {  // B: 2048 segs
            int seg = tid + i * 512;
            int row = seg >> 3, sc = seg & 7;
            uint32_t soff = row * G1_P + sc * 16;
            size_t gB = (size_t)(bcol + row) * IN_DIM + k0 + sc * 8;
            cp_async16(s0 + BOFF + soff, g_w1t + gB, 16);
        }
        cp_commit();
    };

    issue_load(0, 0);
    issue_load(1, 1);

    for (int kc = 0; kc < G1_NKC; kc++) {
        if (kc == G1_NKC - 1) cp_wait<0>(); else cp_wait<1>();
        __syncthreads();
        if (kc + 2 < G1_NKC) issue_load(kc + 2, (kc + 2) % 3);

        const uint32_t s0 = sbase + (kc % 3) * G1_ST;
#pragma unroll
        for (int ks = 0; ks < 4; ks++) {
            uint32_t a[2][4];
            const int ac = (ks * 16 + (lane >> 4) * 8) * 2;
#pragma unroll
            for (int mt = 0; mt < 2; mt++) {
                int r = wm * 32 + mt * 16 + (lane & 15);
                ldsm_x4(a[mt], s0 + AOFF + r * G1_P + ac);
            }
            const int bn_l = (lane >> 4) * 8 + (lane & 7);
            const int bk   = (ks * 16 + ((lane >> 3) & 1) * 8) * 2;
#pragma unroll
            for (int p = 0; p < 4; p++) {
                uint32_t b[4];
                int n = wn * 64 + p * 16 + bn_l;
                ldsm_x4(b, s0 + BOFF + n * G1_P + bk);
#pragma unroll
                for (int mt = 0; mt < 2; mt++) {
#pragma unroll
                    for (int j = 0; j < 2; j++)
                        mma_f16(d[mt][2 * p + j], a[mt], b + 2 * j);
                }
            }
        }
    }

    // ---- epilogue: relu(acc + bias) -> fp16 h1
#pragma unroll
    for (int mt = 0; mt < 2; mt++) {
        int row0 = brow + wm * 32 + mt * 16 + (lane >> 2);
#pragma unroll
        for (int nt = 0; nt < 8; nt++) {
            int col = bcol + wn * 64 + nt * 8 + (lane & 3) * 2;
            float b0 = bias[col], b1 = bias[col + 1];
#pragma unroll
            for (int h = 0; h < 2; h++) {
                int r = row0 + h * 8;
                if (r >= M) continue;
                __half2 hv = __floats2half2_rn(fmaxf(d[mt][nt][2 * h + 0] + b0, 0.f),
                                               fmaxf(d[mt][nt][2 * h + 1] + b1, 0.f));
                *(__half2*)(g_h1h + (size_t)r * HID_DIM + col) = hv;
            }
        }
    }
}

// ============ GEMM2 (mma.sync fp16): H0 = h1 @ W2 + b2 -> fp16 ============
#define G2_NKC   (HID_DIM / 64)       // 8
#define G2_P     144
#define G2_AT    (128 * G2_P)         // 18432
#define G2_BT    (64 * G2_P)          // 9216
#define G2_ST    (G2_AT + G2_BT)      // 27648
#define G2_SMEM  (3 * G2_ST)          // 82944

__global__ __launch_bounds__(256, 1) void gemm2_mma_kernel(const float* __restrict__ bias, int M)
{
    extern __shared__ char smem[];
    const int tid  = threadIdx.x;
    const int wid  = tid >> 5, lane = tid & 31;
    const int wm   = wid & 3,  wn   = wid >> 2;      // 4 x 2 warps
    const int brow = blockIdx.x * 128;

    const uint32_t sbase = smem_u32(smem);
    const uint32_t AOFF = 0, BOFF = G2_AT;

    float d[2][4][4];
#pragma unroll
    for (int i = 0; i < 2; i++)
#pragma unroll
        for (int j = 0; j < 4; j++)
#pragma unroll
            for (int k = 0; k < 4; k++) d[i][j][k] = 0.f;

    auto issue_load = [&](int kc, int st) {
        const int k0 = kc * 64;
        const uint32_t s0 = sbase + st * G2_ST;
#pragma unroll
        for (int i = 0; i < 4; i++) {  // A: 1024 segs
            int seg = tid + i * 256;
            int row = seg >> 3, sc = seg & 7;
            uint32_t soff = row * G2_P + sc * 16;
            int ar = brow + row;
            int ok = (ar < M);
            size_t gA = (size_t)(ok ? ar : 0) * HID_DIM + k0 + sc * 8;
            cp_async16(s0 + AOFF + soff, g_h1h + gA, ok ? 16 : 0);
        }
#pragma unroll
        for (int i = 0; i < 2; i++) {  // B: 512 segs
            int seg = tid + i * 256;
            int row = seg >> 3, sc = seg & 7;
            uint32_t soff = row * G2_P + sc * 16;
            size_t gB = (size_t)row * HID_DIM + k0 + sc * 8;
            cp_async16(s0 + BOFF + soff, g_w2t + gB, 16);
        }
        cp_commit();
    };

    issue_load(0, 0);
    issue_load(1, 1);

    for (int kc = 0; kc < G2_NKC; kc++) {
        if (kc == G2_NKC - 1) cp_wait<0>(); else cp_wait<1>();
        __syncthreads();
        if (kc + 2 < G2_NKC) issue_load(kc + 2, (kc + 2) % 3);

        const uint32_t s0 = sbase + (kc % 3) * G2_ST;
#pragma unroll
        for (int ks = 0; ks < 4; ks++) {
            uint32_t a[2][4];
            const int ac = (ks * 16 + (lane >> 4) * 8) * 2;
#pragma unroll
            for (int mt = 0; mt < 2; mt++) {
                int r = wm * 32 + mt * 16 + (lane & 15);
                ldsm_x4(a[mt], s0 + AOFF + r * G2_P + ac);
            }
            const int bn_l = (lane >> 4) * 8 + (lane & 7);
            const int bk   = (ks * 16 + ((lane >> 3) & 1) * 8) * 2;
#pragma unroll
            for (int p = 0; p < 2; p++) {
                uint32_t b[4];
                int n = wn * 32 + p * 16 + bn_l;
                ldsm_x4(b, s0 + BOFF + n * G2_P + bk);
#pragma unroll
                for (int mt = 0; mt < 2; mt++) {
#pragma unroll
                    for (int j = 0; j < 2; j++)
                        mma_f16(d[mt][2 * p + j], a[mt], b + 2 * j);
                }
            }
        }
    }

    // ---- epilogue: + bias, write fp16 H0
#pragma unroll
    for (int mt = 0; mt < 2; mt++) {
        int row0 = brow + wm * 32 + mt * 16 + (lane >> 2);
#pragma unroll
        for (int nt = 0; nt < 4; nt++) {
            int col = wn * 32 + nt * 8 + (lane & 3) * 2;
            float b0 = bias[col], b1 = bias[col + 1];
#pragma unroll
            for (int h = 0; h < 2; h++) {
                int r = row0 + h * 8;
                if (r >= M) continue;
                __half2 hv = __floats2half2_rn(d[mt][nt][2 * h + 0] + b0,
                                               d[mt][nt][2 * h + 1] + b1);
                *(__half2*)(g_Hh + (size_t)r * OUT_DIM + col) = hv;
            }
        }
    }
}

// ---------------- CSR build ----------------
__global__ void zero_deg_kernel(int n)
{
    int i = blockIdx.x * blockDim.x + threadIdx.x;
    if (i < n) g_deg[i] = 0;
}

__global__ void hist_kernel(const int* __restrict__ row, int E)
{
    int e = blockIdx.x * blockDim.x + threadIdx.x;
    if (e < E) atomicAdd(&g_deg[row[e]], 1);
}

__global__ __launch_bounds__(1024) void scan_kernel(int n)
{
    __shared__ int sums[1024];
    int tid = threadIdx.x;
    int per = (n + 1023) >> 10;
    int start = tid * per;
    int end = min(start + per, n);

    int s = 0;
    for (int i = start; i < end; ++i) s += g_deg[i];
    sums[tid] = s;
    __syncthreads();

    for (int off = 1; off < 1024; off <<= 1) {
        int v = 0;
        if (tid >= off) v = sums[tid - off];
        __syncthreads();
        sums[tid] += v;
        __syncthreads();
    }

    int run = sums[tid] - s;
    for (int i = start; i < end; ++i) {
        g_rowptr[i] = run;
        g_cursor[i] = run;
        run += g_deg[i];
    }
    if (tid == 1023) g_rowptr[n] = sums[1023];
}

__global__ void scatter_kernel(const int* __restrict__ row, const int* __restrict__ col,
                               const float* __restrict__ w, int E)
{
    int e = blockIdx.x * blockDim.x + threadIdx.x;
    if (e >= E) return;
    int r = row[e];
    int pos = atomicAdd(&g_cursor[r], 1);
    __half hw = __float2half_rn(w[e]);
    __half2 w2 = __half2half2(hw);
    g_edge[pos] = make_int2(col[e], h22bits(w2));
}

// ---------------- SpMM hop: 4 edges per LDG.128 ----------------
// warp per row; lane = (grp, sub): grp = edge slot (4 concurrent edges),
// sub = 16B feature segment (8 subs x 16B = full 128B row).
__global__ __launch_bounds__(256) void spmm_kernel(int hop, int n)
{
    __shared__ int2 ebuf[8][32];
    const int wslot = threadIdx.x >> 5;
    const int warp  = (blockIdx.x * blockDim.x + threadIdx.x) >> 5;
    const int lane  = threadIdx.x & 31;
    if (warp >= n) return;
    const int grp = lane >> 3;
    const int sub = lane & 7;

    const __half* __restrict__ hin = g_Hh + (size_t)(hop - 1) * N_NODES * OUT_DIM;
    __half* __restrict__ hout      = g_Hh + (size_t)hop * N_NODES * OUT_DIM;

    const int s = g_rowptr[warp];
    const int e = g_rowptr[warp + 1];

    float f[8];
#pragma unroll
    for (int k = 0; k < 8; k++) f[k] = 0.f;

    for (int base = s; base < e; base += 32) {
        const int cnt = min(32, e - base);
        if (lane < cnt) ebuf[wslot][lane] = g_edge[base + lane];
        __syncwarp();

        __half2 hacc[4];
#pragma unroll
        for (int k = 0; k < 4; k++) hacc[k] = __float2half2_rn(0.f);

        const int nit = (cnt + 3) >> 2;
        for (int it = 0; it < nit; ++it) {
            int ei = it * 4 + grp;
            int2 ed = ebuf[wslot][ei < cnt ? ei : 0];
            int wb  = (ei < cnt) ? ed.y : 0;
            uint4 v = *(const uint4*)(hin + (size_t)ed.x * 64 + sub * 8);
            __half2 w2 = bits2h2(wb);
            hacc[0] = __hfma2(w2, bits2h2((int)v.x), hacc[0]);
            hacc[1] = __hfma2(w2, bits2h2((int)v.y), hacc[1]);
            hacc[2] = __hfma2(w2, bits2h2((int)v.z), hacc[2]);
            hacc[3] = __hfma2(w2, bits2h2((int)v.w), hacc[3]);
        }
#pragma unroll
        for (int k = 0; k < 4; k++) {
            float2 t = __half22float2(hacc[k]);
            f[2 * k]     += t.x;
            f[2 * k + 1] += t.y;
        }
        __syncwarp();
    }

    // reduce across the 4 edge groups
#pragma unroll
    for (int k = 0; k < 8; k++) {
        f[k] += __shfl_xor_sync(0xffffffffu, f[k], 8);
        f[k] += __shfl_xor_sync(0xffffffffu, f[k], 16);
    }
    if (grp == 0) {
        union { __half2 h[4]; uint4 u; } o;
#pragma unroll
        for (int k = 0; k < 4; k++)
            o.h[k] = __floats2half2_rn(f[2 * k], f[2 * k + 1]);
        *(uint4*)(hout + (size_t)warp * 64 + sub * 8) = o.u;
    }
}

// ---------------- Combine ----------------
__global__ __launch_bounds__(256) void combine_kernel(
    const float* __restrict__ s, float* __restrict__ out, int n)
{
    int warp = (blockIdx.x * blockDim.x + threadIdx.x) >> 5;
    int lane = threadIdx.x & 31;
    if (warp >= n) return;

    float s0 = s[lane * 2 + 0];
    float s1 = s[lane * 2 + 1];

    float ox = 0.f, oy = 0.f;
#pragma unroll
    for (int k = 0; k <= HOPS; k++) {
        const __half2* hk = (const __half2*)(g_Hh + (size_t)k * N_NODES * OUT_DIM);
        float2 h = __half22float2(hk[(size_t)warp * 32 + lane]);
        float d = h.x * s0 + h.y * s1;
#pragma unroll
        for (int off = 16; off; off >>= 1) d += __shfl_xor_sync(0xffffffffu, d, off);
        float sg = 1.f / (1.f + expf(-d));
        ox += sg * h.x;
        oy += sg * h.y;
    }
    ((float2*)out)[(size_t)warp * 32 + lane] = make_float2(ox, oy);
}

// ---------------- launch ----------------
extern "C" void kernel_launch(void* const* d_in, const int* in_sizes, int n_in,
                              void* d_out, int out_size)
{
    const float* x   = (const float*)d_in[0];
    const int*   row = (const int*)  d_in[1];
    const int*   col = (const int*)  d_in[2];
    const float* ew  = (const float*)d_in[3];
    const float* W1  = (const float*)d_in[4];
    const float* b1  = (const float*)d_in[5];
    const float* W2  = (const float*)d_in[6];
    const float* b2  = (const float*)d_in[7];
    const float* s   = (const float*)d_in[8];

    int M = in_sizes[0] / IN_DIM;  // 100000
    int E = in_sizes[1];           // 3300000

    static bool attr_set = false;
    if (!attr_set) {
        cudaFuncSetAttribute(gemm1_mma_kernel,
                             cudaFuncAttributeMaxDynamicSharedMemorySize, G1_SMEM);
        cudaFuncSetAttribute(gemm2_mma_kernel,
                             cudaFuncAttributeMaxDynamicSharedMemorySize, G2_SMEM);
        attr_set = true;
    }

    // fp16 conversions
    size_t n4 = (size_t)M * IN_DIM / 4;
    conv_x_kernel<<<(unsigned)((n4 + 255) / 256), 256>>>(x, n4);
    conv_w1_kernel<<<(HID_DIM * IN_DIM + 255) / 256, 256>>>(W1);
    conv_w2_kernel<<<(OUT_DIM * HID_DIM + 255) / 256, 256>>>(W2);

    // dense front-end on tensor cores (gemm1 = launch index 3 for profiling)
    dim3 g1((M + 127) / 128, HID_DIM / 256);
    gemm1_mma_kernel<<<g1, 512, G1_SMEM>>>(b1, M);
    gemm2_mma_kernel<<<(M + 127) / 128, 256, G2_SMEM>>>(b2, M);

    // CSR build
    zero_deg_kernel<<<(M + 255) / 256, 256>>>(M);
    hist_kernel<<<(E + 255) / 256, 256>>>(row, E);
    scan_kernel<<<1, 1024>>>(M);
    scatter_kernel<<<(E + 255) / 256, 256>>>(row, col, ew, E);

    // 10 propagation hops (fp16 features)
    int spmm_blocks = (M * 32 + 255) / 256;
    for (int hop = 1; hop <= HOPS; ++hop)
        spmm_kernel<<<spmm_blocks, 256>>>(hop, M);

    // gated combine
    combine_kernel<<<spmm_blocks, 256>>>(s, (float*)d_out, M);
}

// round 8
// speedup vs baseline: 3.0005x; 1.2446x over previous
#include <cuda_runtime.h>
#include <cuda_fp16.h>
#include <math.h>
#include <stdint.h>

#define N_NODES 100000
#define E_MAX   3300000
#define IN_DIM  512
#define HID_DIM 512
#define OUT_DIM 64
#define HOPS    10

// ---------------- scratch (static device globals; no allocations) ----------------
__device__ __half g_xh[(size_t)N_NODES * IN_DIM];                 // 102.4 MB
__device__ __half g_h1h[(size_t)N_NODES * HID_DIM];               // 102.4 MB
__device__ __half g_Hh[(size_t)(HOPS + 1) * N_NODES * OUT_DIM];   // 140.8 MB
__device__ __half g_w1t[(size_t)HID_DIM * IN_DIM];                // 0.5 MB ([n][k])
__device__ __half g_w2t[(size_t)OUT_DIM * HID_DIM];               // 64 KB ([n][k])
__device__ int   g_deg[N_NODES];
__device__ int   g_rowptr[N_NODES + 1];
__device__ int   g_cursor[N_NODES];
__device__ int2  g_edge[E_MAX];                                   // (col, half2(w,w) bits)

// ================= PTX helpers =================
__device__ __forceinline__ uint32_t smem_u32(const void* p) {
    uint32_t a;
    asm("{ .reg .u64 t; cvta.to.shared.u64 t, %1; cvt.u32.u64 %0, t; }" : "=r"(a) : "l"(p));
    return a;
}
__device__ __forceinline__ void cp_async16(uint32_t s, const void* g, int sz) {
    asm volatile("cp.async.cg.shared.global [%0], [%1], 16, %2;"
                 :: "r"(s), "l"(g), "r"(sz) : "memory");
}
__device__ __forceinline__ void cp_commit() {
    asm volatile("cp.async.commit_group;" ::: "memory");
}
template <int N>
__device__ __forceinline__ void cp_wait() {
    asm volatile("cp.async.wait_group %0;" :: "n"(N) : "memory");
}
__device__ __forceinline__ void ldsm_x4(uint32_t* r, uint32_t addr) {
    asm volatile("ldmatrix.sync.aligned.m8n8.x4.shared.b16 {%0,%1,%2,%3}, [%4];"
                 : "=r"(r[0]), "=r"(r[1]), "=r"(r[2]), "=r"(r[3]) : "r"(addr));
}
__device__ __forceinline__ void mma_f16(float* d, const uint32_t* a, const uint32_t* b) {
    asm volatile(
        "mma.sync.aligned.m16n8k16.row.col.f32.f16.f16.f32 "
        "{%0,%1,%2,%3}, {%4,%5,%6,%7}, {%8,%9}, {%0,%1,%2,%3};"
        : "+f"(d[0]), "+f"(d[1]), "+f"(d[2]), "+f"(d[3])
        : "r"(a[0]), "r"(a[1]), "r"(a[2]), "r"(a[3]), "r"(b[0]), "r"(b[1]));
}
__device__ __forceinline__ __half2 bits2h2(int b) {
    union { int i; __half2 h; } u; u.i = b; return u.h;
}
__device__ __forceinline__ int h22bits(__half2 h) {
    union { int i; __half2 h; } u; u.h = h; return u.i;
}

// ---------------- fp16 conversion kernels ----------------
__global__ void conv_x_kernel(const float* __restrict__ x, size_t n4)
{
    size_t i = (size_t)blockIdx.x * blockDim.x + threadIdx.x;
    if (i >= n4) return;
    float4 v = *(const float4*)(x + i * 4);
    union { __half2 h[2]; uint2 u; } o;
    o.h[0] = __floats2half2_rn(v.x, v.y);
    o.h[1] = __floats2half2_rn(v.z, v.w);
    *(uint2*)(g_xh + i * 4) = o.u;
}

__global__ void conv_w1_kernel(const float* __restrict__ W1)
{
    int i = blockIdx.x * blockDim.x + threadIdx.x;  // i = n*512 + k
    if (i >= HID_DIM * IN_DIM) return;
    int n = i >> 9, k = i & 511;
    g_w1t[i] = __float2half_rn(W1[k * HID_DIM + n]);
}

__global__ void conv_w2_kernel(const float* __restrict__ W2)
{
    int i = blockIdx.x * blockDim.x + threadIdx.x;  // i = n*512 + k
    if (i >= OUT_DIM * HID_DIM) return;
    int n = i >> 9, k = i & 511;
    g_w2t[i] = __float2half_rn(W2[k * OUT_DIM + n]);
}

// ============ GEMM1 (mma.sync fp16): h1 = relu(x @ W1 + b1) -> fp16 ============
// CTA 128x256, 16 warps (4M x 4N), warp tile 32x64. K chunks of 64, 3-stage.
#define G1_NKC   (IN_DIM / 64)        // 8
#define G1_P     144
#define G1_AT    (128 * G1_P)         // 18432
#define G1_BT    (256 * G1_P)         // 36864
#define G1_ST    (G1_AT + G1_BT)      // 55296
#define G1_SMEM  (3 * G1_ST)          // 165888

__global__ __launch_bounds__(512, 1) void gemm1_mma_kernel(const float* __restrict__ bias, int M)
{
    extern __shared__ char smem[];
    const int tid  = threadIdx.x;
    const int wid  = tid >> 5, lane = tid & 31;
    const int wm   = wid & 3,  wn   = wid >> 2;      // 4 x 4 warps
    const int brow = blockIdx.x * 128, bcol = blockIdx.y * 256;

    const uint32_t sbase = smem_u32(smem);
    const uint32_t AOFF = 0, BOFF = G1_AT;

    float d[2][8][4];
#pragma unroll
    for (int i = 0; i < 2; i++)
#pragma unroll
        for (int j = 0; j < 8; j++)
#pragma unroll
            for (int k = 0; k < 4; k++) d[i][j][k] = 0.f;

    auto issue_load = [&](int kc, int st) {
        const int k0 = kc * 64;
        const uint32_t s0 = sbase + st * G1_ST;
#pragma unroll
        for (int i = 0; i < 2; i++) {  // A: 1024 segs of 16B
            int seg = tid + i * 512;
            int row = seg >> 3, sc = seg & 7;
            uint32_t soff = row * G1_P + sc * 16;
            int ar = brow + row;
            int ok = (ar < M);
            size_t gA = (size_t)(ok ? ar : 0) * IN_DIM + k0 + sc * 8;
            cp_async16(s0 + AOFF + soff, g_xh + gA, ok ? 16 : 0);
        }
#pragma unroll
        for (int i = 0; i < 4; i++) {  // B: 2048 segs
            int seg = tid + i * 512;
            int row = seg >> 3, sc = seg & 7;
            uint32_t soff = row * G1_P + sc * 16;
            size_t gB = (size_t)(bcol + row) * IN_DIM + k0 + sc * 8;
            cp_async16(s0 + BOFF + soff, g_w1t + gB, 16);
        }
        cp_commit();
    };

    issue_load(0, 0);
    issue_load(1, 1);

    for (int kc = 0; kc < G1_NKC; kc++) {
        if (kc == G1_NKC - 1) cp_wait<0>(); else cp_wait<1>();
        __syncthreads();
        if (kc + 2 < G1_NKC) issue_load(kc + 2, (kc + 2) % 3);

        const uint32_t s0 = sbase + (kc % 3) * G1_ST;
#pragma unroll
        for (int ks = 0; ks < 4; ks++) {
            uint32_t a[2][4];
            const int ac = (ks * 16 + (lane >> 4) * 8) * 2;
#pragma unroll
            for (int mt = 0; mt < 2; mt++) {
                int r = wm * 32 + mt * 16 + (lane & 15);
                ldsm_x4(a[mt], s0 + AOFF + r * G1_P + ac);
            }
            const int bn_l = (lane >> 4) * 8 + (lane & 7);
            const int bk   = (ks * 16 + ((lane >> 3) & 1) * 8) * 2;
#pragma unroll
            for (int p = 0; p < 4; p++) {
                uint32_t b[4];
                int n = wn * 64 + p * 16 + bn_l;
                ldsm_x4(b, s0 + BOFF + n * G1_P + bk);
#pragma unroll
                for (int mt = 0; mt < 2; mt++) {
#pragma unroll
                    for (int j = 0; j < 2; j++)
                        mma_f16(d[mt][2 * p + j], a[mt], b + 2 * j);
                }
            }
        }
    }

    // ---- epilogue: relu(acc + bias) -> fp16 h1
#pragma unroll
    for (int mt = 0; mt < 2; mt++) {
        int row0 = brow + wm * 32 + mt * 16 + (lane >> 2);
#pragma unroll
        for (int nt = 0; nt < 8; nt++) {
            int col = bcol + wn * 64 + nt * 8 + (lane & 3) * 2;
            float b0 = bias[col], b1 = bias[col + 1];
#pragma unroll
            for (int h = 0; h < 2; h++) {
                int r = row0 + h * 8;
                if (r >= M) continue;
                __half2 hv = __floats2half2_rn(fmaxf(d[mt][nt][2 * h + 0] + b0, 0.f),
                                               fmaxf(d[mt][nt][2 * h + 1] + b1, 0.f));
                *(__half2*)(g_h1h + (size_t)r * HID_DIM + col) = hv;
            }
        }
    }
}

// ============ GEMM2 (mma.sync fp16): H0 = h1 @ W2 + b2 -> fp16 ============
#define G2_NKC   (HID_DIM / 64)       // 8
#define G2_P     144
#define G2_AT    (128 * G2_P)         // 18432
#define G2_BT    (64 * G2_P)          // 9216
#define G2_ST    (G2_AT + G2_BT)      // 27648
#define G2_SMEM  (3 * G2_ST)          // 82944

__global__ __launch_bounds__(256, 1) void gemm2_mma_kernel(const float* __restrict__ bias, int M)
{
    extern __shared__ char smem[];
    const int tid  = threadIdx.x;
    const int wid  = tid >> 5, lane = tid & 31;
    const int wm   = wid & 3,  wn   = wid >> 2;      // 4 x 2 warps
    const int brow = blockIdx.x * 128;

    const uint32_t sbase = smem_u32(smem);
    const uint32_t AOFF = 0, BOFF = G2_AT;

    float d[2][4][4];
#pragma unroll
    for (int i = 0; i < 2; i++)
#pragma unroll
        for (int j = 0; j < 4; j++)
#pragma unroll
            for (int k = 0; k < 4; k++) d[i][j][k] = 0.f;

    auto issue_load = [&](int kc, int st) {
        const int k0 = kc * 64;
        const uint32_t s0 = sbase + st * G2_ST;
#pragma unroll
        for (int i = 0; i < 4; i++) {  // A: 1024 segs
            int seg = tid + i * 256;
            int row = seg >> 3, sc = seg & 7;
            uint32_t soff = row * G2_P + sc * 16;
            int ar = brow + row;
            int ok = (ar < M);
            size_t gA = (size_t)(ok ? ar : 0) * HID_DIM + k0 + sc * 8;
            cp_async16(s0 + AOFF + soff, g_h1h + gA, ok ? 16 : 0);
        }
#pragma unroll
        for (int i = 0; i < 2; i++) {  // B: 512 segs
            int seg = tid + i * 256;
            int row = seg >> 3, sc = seg & 7;
            uint32_t soff = row * G2_P + sc * 16;
            size_t gB = (size_t)row * HID_DIM + k0 + sc * 8;
            cp_async16(s0 + BOFF + soff, g_w2t + gB, 16);
        }
        cp_commit();
    };

    issue_load(0, 0);
    issue_load(1, 1);

    for (int kc = 0; kc < G2_NKC; kc++) {
        if (kc == G2_NKC - 1) cp_wait<0>(); else cp_wait<1>();
        __syncthreads();
        if (kc + 2 < G2_NKC) issue_load(kc + 2, (kc + 2) % 3);

        const uint32_t s0 = sbase + (kc % 3) * G2_ST;
#pragma unroll
        for (int ks = 0; ks < 4; ks++) {
            uint32_t a[2][4];
            const int ac = (ks * 16 + (lane >> 4) * 8) * 2;
#pragma unroll
            for (int mt = 0; mt < 2; mt++) {
                int r = wm * 32 + mt * 16 + (lane & 15);
                ldsm_x4(a[mt], s0 + AOFF + r * G2_P + ac);
            }
            const int bn_l = (lane >> 4) * 8 + (lane & 7);
            const int bk   = (ks * 16 + ((lane >> 3) & 1) * 8) * 2;
#pragma unroll
            for (int p = 0; p < 2; p++) {
                uint32_t b[4];
                int n = wn * 32 + p * 16 + bn_l;
                ldsm_x4(b, s0 + BOFF + n * G2_P + bk);
#pragma unroll
                for (int mt = 0; mt < 2; mt++) {
#pragma unroll
                    for (int j = 0; j < 2; j++)
                        mma_f16(d[mt][2 * p + j], a[mt], b + 2 * j);
                }
            }
        }
    }

    // ---- epilogue: + bias, write fp16 H0
#pragma unroll
    for (int mt = 0; mt < 2; mt++) {
        int row0 = brow + wm * 32 + mt * 16 + (lane >> 2);
#pragma unroll
        for (int nt = 0; nt < 4; nt++) {
            int col = wn * 32 + nt * 8 + (lane & 3) * 2;
            float b0 = bias[col], b1 = bias[col + 1];
#pragma unroll
            for (int h = 0; h < 2; h++) {
                int r = row0 + h * 8;
                if (r >= M) continue;
                __half2 hv = __floats2half2_rn(d[mt][nt][2 * h + 0] + b0,
                                               d[mt][nt][2 * h + 1] + b1);
                *(__half2*)(g_Hh + (size_t)r * OUT_DIM + col) = hv;
            }
        }
    }
}

// ---------------- CSR build ----------------
__global__ void zero_deg_kernel(int n)
{
    int i = blockIdx.x * blockDim.x + threadIdx.x;
    if (i < n) g_deg[i] = 0;
}

__global__ void hist_kernel(const int* __restrict__ row, int E)
{
    int e = blockIdx.x * blockDim.x + threadIdx.x;
    if (e < E) atomicAdd(&g_deg[row[e]], 1);
}

__global__ __launch_bounds__(1024) void scan_kernel(int n)
{
    __shared__ int sums[1024];
    int tid = threadIdx.x;
    int per = (n + 1023) >> 10;
    int start = tid * per;
    int end = min(start + per, n);

    int s = 0;
    for (int i = start; i < end; ++i) s += g_deg[i];
    sums[tid] = s;
    __syncthreads();

    for (int off = 1; off < 1024; off <<= 1) {
        int v = 0;
        if (tid >= off) v = sums[tid - off];
        __syncthreads();
        sums[tid] += v;
        __syncthreads();
    }

    int run = sums[tid] - s;
    for (int i = start; i < end; ++i) {
        g_rowptr[i] = run;
        g_cursor[i] = run;
        run += g_deg[i];
    }
    if (tid == 1023) g_rowptr[n] = sums[1023];
}

__global__ void scatter_kernel(const int* __restrict__ row, const int* __restrict__ col,
                               const float* __restrict__ w, int E)
{
    int e = blockIdx.x * blockDim.x + threadIdx.x;
    if (e >= E) return;
    int r = row[e];
    int pos = atomicAdd(&g_cursor[r], 1);
    __half hw = __float2half_rn(w[e]);
    __half2 w2 = __half2half2(hw);
    g_edge[pos] = make_int2(col[e], h22bits(w2));
}

// ---------------- SpMM hop: 4 edges per LDG.128, MLP-8 fast path ----------------
__global__ __launch_bounds__(256) void spmm_kernel(int hop, int n)
{
    __shared__ int2 ebuf[8][32];
    const int wslot = threadIdx.x >> 5;
    const int warp  = (blockIdx.x * blockDim.x + threadIdx.x) >> 5;
    const int lane  = threadIdx.x & 31;
    if (warp >= n) return;
    const int grp = lane >> 3;
    const int sub = lane & 7;

    const __half* __restrict__ hin = g_Hh + (size_t)(hop - 1) * N_NODES * OUT_DIM;
    __half* __restrict__ hout      = g_Hh + (size_t)hop * N_NODES * OUT_DIM;

    const int s = g_rowptr[warp];
    const int e = g_rowptr[warp + 1];

    float f[8];
#pragma unroll
    for (int k = 0; k < 8; k++) f[k] = 0.f;

    for (int base = s; base < e; base += 32) {
        const int cnt = min(32, e - base);
        if (lane < cnt) ebuf[wslot][lane] = g_edge[base + lane];
        __syncwarp();

        __half2 hacc[4];
#pragma unroll
        for (int k = 0; k < 4; k++) hacc[k] = __float2half2_rn(0.f);

        if (cnt == 32) {
            // full batch: unrolled -> 8 independent LDG.128 in flight (MLP 8)
#pragma unroll
            for (int it = 0; it < 8; ++it) {
                int2 ed = ebuf[wslot][it * 4 + grp];
                uint4 v = *(const uint4*)(hin + (size_t)ed.x * 64 + sub * 8);
                __half2 w2 = bits2h2(ed.y);
                hacc[0] = __hfma2(w2, bits2h2((int)v.x), hacc[0]);
                hacc[1] = __hfma2(w2, bits2h2((int)v.y), hacc[1]);
                hacc[2] = __hfma2(w2, bits2h2((int)v.z), hacc[2]);
                hacc[3] = __hfma2(w2, bits2h2((int)v.w), hacc[3]);
            }
        } else {
            const int nit = (cnt + 3) >> 2;
            for (int it = 0; it < nit; ++it) {
                int ei = it * 4 + grp;
                int2 ed = ebuf[wslot][ei < cnt ? ei : 0];
                int wb  = (ei < cnt) ? ed.y : 0;
                uint4 v = *(const uint4*)(hin + (size_t)ed.x * 64 + sub * 8);
                __half2 w2 = bits2h2(wb);
                hacc[0] = __hfma2(w2, bits2h2((int)v.x), hacc[0]);
                hacc[1] = __hfma2(w2, bits2h2((int)v.y), hacc[1]);
                hacc[2] = __hfma2(w2, bits2h2((int)v.z), hacc[2]);
                hacc[3] = __hfma2(w2, bits2h2((int)v.w), hacc[3]);
            }
        }
#pragma unroll
        for (int k = 0; k < 4; k++) {
            float2 t = __half22float2(hacc[k]);
            f[2 * k]     += t.x;
            f[2 * k + 1] += t.y;
        }
        __syncwarp();
    }

    // reduce across the 4 edge groups
#pragma unroll
    for (int k = 0; k < 8; k++) {
        f[k] += __shfl_xor_sync(0xffffffffu, f[k], 8);
        f[k] += __shfl_xor_sync(0xffffffffu, f[k], 16);
    }
    if (grp == 0) {
        union { __half2 h[4]; uint4 u; } o;
#pragma unroll
        for (int k = 0; k < 4; k++)
            o.h[k] = __floats2half2_rn(f[2 * k], f[2 * k + 1]);
        *(uint4*)(hout + (size_t)warp * 64 + sub * 8) = o.u;
    }
}

// ---------------- Combine ----------------
__global__ __launch_bounds__(256) void combine_kernel(
    const float* __restrict__ s, float* __restrict__ out, int n)
{
    int warp = (blockIdx.x * blockDim.x + threadIdx.x) >> 5;
    int lane = threadIdx.x & 31;
    if (warp >= n) return;

    float s0 = s[lane * 2 + 0];
    float s1 = s[lane * 2 + 1];

    float ox = 0.f, oy = 0.f;
#pragma unroll
    for (int k = 0; k <= HOPS; k++) {
        const __half2* hk = (const __half2*)(g_Hh + (size_t)k * N_NODES * OUT_DIM);
        float2 h = __half22float2(hk[(size_t)warp * 32 + lane]);
        float d = h.x * s0 + h.y * s1;
#pragma unroll
        for (int off = 16; off; off >>= 1) d += __shfl_xor_sync(0xffffffffu, d, off);
        float sg = 1.f / (1.f + expf(-d));
        ox += sg * h.x;
        oy += sg * h.y;
    }
    ((float2*)out)[(size_t)warp * 32 + lane] = make_float2(ox, oy);
}

// ---------------- launch ----------------
extern "C" void kernel_launch(void* const* d_in, const int* in_sizes, int n_in,
                              void* d_out, int out_size)
{
    const float* x   = (const float*)d_in[0];
    const int*   row = (const int*)  d_in[1];
    const int*   col = (const int*)  d_in[2];
    const float* ew  = (const float*)d_in[3];
    const float* W1  = (const float*)d_in[4];
    const float* b1  = (const float*)d_in[5];
    const float* W2  = (const float*)d_in[6];
    const float* b2  = (const float*)d_in[7];
    const float* s   = (const float*)d_in[8];

    int M = in_sizes[0] / IN_DIM;  // 100000
    int E = in_sizes[1];           // 3300000

    static bool attr_set = false;
    static cudaStream_t s_csr = 0;
    static cudaEvent_t ev_fork = 0, ev_join = 0;
    if (!attr_set) {
        cudaFuncSetAttribute(gemm1_mma_kernel,
                             cudaFuncAttributeMaxDynamicSharedMemorySize, G1_SMEM);
        cudaFuncSetAttribute(gemm2_mma_kernel,
                             cudaFuncAttributeMaxDynamicSharedMemorySize, G2_SMEM);
        cudaStreamCreateWithFlags(&s_csr, cudaStreamNonBlocking);
        cudaEventCreateWithFlags(&ev_fork, cudaEventDisableTiming);
        cudaEventCreateWithFlags(&ev_join, cudaEventDisableTiming);
        attr_set = true;
    }

    // ---- fork: CSR build runs concurrently with conversions + GEMMs ----
    cudaEventRecord(ev_fork, 0);
    cudaStreamWaitEvent(s_csr, ev_fork, 0);
    zero_deg_kernel<<<(M + 255) / 256, 256, 0, s_csr>>>(M);
    hist_kernel<<<(E + 255) / 256, 256, 0, s_csr>>>(row, E);
    scan_kernel<<<1, 1024, 0, s_csr>>>(M);
    scatter_kernel<<<(E + 255) / 256, 256, 0, s_csr>>>(row, col, ew, E);
    cudaEventRecord(ev_join, s_csr);

    // main stream: fp16 conversions + GEMMs
    size_t n4 = (size_t)M * IN_DIM / 4;
    conv_x_kernel<<<(unsigned)((n4 + 255) / 256), 256>>>(x, n4);
    conv_w1_kernel<<<(HID_DIM * IN_DIM + 255) / 256, 256>>>(W1);
    conv_w2_kernel<<<(OUT_DIM * HID_DIM + 255) / 256, 256>>>(W2);

    dim3 g1((M + 127) / 128, HID_DIM / 256);
    gemm1_mma_kernel<<<g1, 512, G1_SMEM>>>(b1, M);
    gemm2_mma_kernel<<<(M + 127) / 128, 256, G2_SMEM>>>(b2, M);

    // ---- join: hops need both the CSR and H0 ----
    cudaStreamWaitEvent(0, ev_join, 0);

    // 10 propagation hops (fp16 features)
    int spmm_blocks = (M * 32 + 255) / 256;
    for (int hop = 1; hop <= HOPS; ++hop)
        spmm_kernel<<<spmm_blocks, 256>>>(hop, M);

    // gated combine
    combine_kernel<<<spmm_blocks, 256>>>(s, (float*)d_out, M);
}